// round 13
// baseline (speedup 1.0000x reference)
#include <cuda_runtime.h>
#include <cuda_fp16.h>
#include <cstdint>

#define BATCH 8
#define NPTS  8192
#define SPTS  2048
#define MTOT  65536
#define CIN   384
#define C0    256
#define C1    128

// ------------------------- device scratch -------------------------
__device__ __half d_Xh[(size_t)MTOT * CIN];          // [m][384] fp16, k-contiguous
__device__ __half d_Y[(size_t)MTOT * C0];            // [m][256] fp16 (raw conv0 out)
__device__ __half d_Z[(size_t)C1 * MTOT];            // [c][m]   fp16 (raw conv1 out)
__device__ float  d_P2T[(size_t)BATCH * SPTS * C0];  // [b][s][256]
__device__ __half d_W0h[C0 * CIN];                   // [256][384]
__device__ __half d_W1h[C1 * C0];                    // [128][256]
__device__ uint4  d_nn[MTOT];
__device__ float  d_stats[768];                      // sum0,sq0 | sum1,sq1

// ------------------------- helpers -------------------------
__device__ __forceinline__ uint32_t smem_u32(const void* p) {
    uint32_t a;
    asm("{ .reg .u64 t; cvta.to.shared.u64 t, %1; cvt.u32.u64 %0, t; }" : "=r"(a) : "l"(p));
    return a;
}
#define SW128(o) ((o) ^ (((o) >> 3) & 0x70))
#define CP_COMMIT() asm volatile("cp.async.commit_group;" ::: "memory")

__device__ __forceinline__ void cp_async16(uint32_t dst, const void* src) {
    size_t g = __cvta_generic_to_global(src);
    asm volatile("cp.async.cg.shared.global [%0], [%1], 16;" :: "r"(dst), "l"(g));
}
__device__ __forceinline__ void ldsm_x4(uint32_t (&r)[4], uint32_t addr) {
    asm volatile("ldmatrix.sync.aligned.m8n8.x4.shared.b16 {%0,%1,%2,%3}, [%4];"
                 : "=r"(r[0]), "=r"(r[1]), "=r"(r[2]), "=r"(r[3]) : "r"(addr));
}
__device__ __forceinline__ void mma_f16(float (&c)[4], const uint32_t (&a)[4],
                                        const uint32_t (&b)[2]) {
    asm volatile(
        "mma.sync.aligned.m16n8k16.row.col.f32.f16.f16.f32 "
        "{%0,%1,%2,%3}, {%4,%5,%6,%7}, {%8,%9}, {%0,%1,%2,%3};"
        : "+f"(c[0]), "+f"(c[1]), "+f"(c[2]), "+f"(c[3])
        : "r"(a[0]), "r"(a[1]), "r"(a[2]), "r"(a[3]), "r"(b[0]), "r"(b[1]));
}
__device__ __forceinline__ uint32_t pack_h2(float v0, float v1) {
    __half2 h = __floats2half2_rn(v0, v1);
    return *reinterpret_cast<uint32_t*>(&h);
}

// ---------------------------------------------------------------------------
// knn insert helper (top-3, sorted ascending)
// ---------------------------------------------------------------------------
__device__ __forceinline__ void knn_insert(float key, int s, float& k0, float& k1,
                                           float& k2, int& i0, int& i1, int& i2)
{
    if (key < k2) {
        if (key < k1) {
            k2 = k1; i2 = i1;
            if (key < k0) { k1 = k0; i1 = i0; k0 = key; i0 = s; }
            else          { k1 = key; i1 = s; }
        } else { k2 = key; i2 = s; }
    }
}
__device__ __forceinline__ void knn_emit(uint4* dst, float k0, float k1, float k2,
                                         int i0, int i1, int i2, float sn)
{
    float r0 = 1.f / (k0 + sn + 1e-8f);
    float r1 = 1.f / (k1 + sn + 1e-8f);
    float r2 = 1.f / (k2 + sn + 1e-8f);
    float ws = r0 + r1 + r2;
    uint4 o;
    o.x = (uint32_t)i0 | ((uint32_t)i1 << 16);
    o.y = (uint32_t)i2;
    o.z = __float_as_uint(r0 / ws);
    o.w = __float_as_uint(r1 / ws);
    *dst = o;
}

// ---------------------------------------------------------------------------
// prep: [0,64) knn (4 pts/thread) | [64,576) points2 transpose |
//       [576,1088) W0/W1 -> fp16 (+ stats zero)
// ---------------------------------------------------------------------------
__global__ __launch_bounds__(256)
void prep_kernel(const float* __restrict__ xyz1, const float* __restrict__ xyz2,
                 const float* __restrict__ points2,
                 const float* __restrict__ w0, const float* __restrict__ w1)
{
    __shared__ __align__(16) char shmem[33280];

    if (blockIdx.x < 64) {
        // ---------------- kNN: 4 query points per thread ----------------
        float4* sp = (float4*)shmem;
        const int bx = blockIdx.x & 7;
        const int b  = blockIdx.x >> 3;
        const int t  = threadIdx.x;

        const float* x2 = xyz2 + (size_t)b * 3 * SPTS;
        for (int s = t; s < SPTS; s += 256) {
            float x = x2[s], y = x2[SPTS + s], z = x2[2 * SPTS + s];
            sp[s] = make_float4(-2.f * x, -2.f * y, -2.f * z, x * x + y * y + z * z);
        }
        __syncthreads();

        const int nA = bx * 1024 + t;
        const float* x1 = xyz1 + (size_t)b * 3 * NPTS;
        float qx[4], qy[4], qz[4];
#pragma unroll
        for (int q = 0; q < 4; q++) {
            qx[q] = x1[nA + q * 256];
            qy[q] = x1[NPTS + nA + q * 256];
            qz[q] = x1[2 * NPTS + nA + q * 256];
        }

        float k0[4], k1[4], k2[4];
        int i0[4], i1[4], i2[4];
#pragma unroll
        for (int q = 0; q < 4; q++) {
            k0[q] = 3.4e38f; k1[q] = 3.4e38f; k2[q] = 3.4e38f;
            i0[q] = 0; i1[q] = 0; i2[q] = 0;
        }

#pragma unroll 2
        for (int s = 0; s < SPTS; ++s) {
            float4 p = sp[s];
#pragma unroll
            for (int q = 0; q < 4; q++) {
                float key = fmaf(p.x, qx[q], fmaf(p.y, qy[q], fmaf(p.z, qz[q], p.w)));
                knn_insert(key, s, k0[q], k1[q], k2[q], i0[q], i1[q], i2[q]);
            }
        }

#pragma unroll
        for (int q = 0; q < 4; q++) {
            float sn = qx[q] * qx[q] + qy[q] * qy[q] + qz[q] * qz[q];
            knn_emit(&d_nn[b * NPTS + nA + q * 256], k0[q], k1[q], k2[q],
                     i0[q], i1[q], i2[q], sn);
        }
    } else if (blockIdx.x < 576) {
        // ---------------- points2 transpose ----------------
        float (*tile)[260] = (float(*)[260])shmem;
        const int tb = blockIdx.x - 64;
        const int b  = tb >> 6;
        const int s0 = (tb & 63) * 32;
        const int tx = threadIdx.x & 31;
        const int ty = threadIdx.x >> 5;

        const float* src = points2 + (size_t)b * C0 * SPTS;
#pragma unroll
        for (int k = 0; k < 32; k++) {
            const int ch = ty + k * 8;
            tile[tx][ch] = src[(size_t)ch * SPTS + s0 + tx];
        }
        __syncthreads();

        const int w = threadIdx.x >> 5, lane = threadIdx.x & 31;
#pragma unroll
        for (int k = 0; k < 4; k++) {
            const int s = w + k * 8;
            float* dst = d_P2T + ((size_t)b * SPTS + s0 + s) * C0;
            *(float4*)(dst + lane * 8)     = *(const float4*)(&tile[s][lane * 8]);
            *(float4*)(dst + lane * 8 + 4) = *(const float4*)(&tile[s][lane * 8 + 4]);
        }
    } else {
        // ---------------- W conversion + stats zero ----------------
        const int wb = blockIdx.x - 576;
        if (wb == 0)
            for (int i = threadIdx.x; i < 768; i += 256) d_stats[i] = 0.f;
        int i = wb * 256 + threadIdx.x;
        if (i < C0 * CIN) d_W0h[i] = __float2half_rn(w0[i]);
        int j = i - C0 * CIN;
        if (j >= 0 && j < C1 * C0) d_W1h[j] = __float2half_rn(w1[j]);
    }
}

// ---------------------------------------------------------------------------
// Fused X-builder: warp-per-point, fp16.
// ---------------------------------------------------------------------------
__global__ __launch_bounds__(256)
void fused_x_kernel(const float* __restrict__ points1)
{
    __shared__ float tile[32][132];
    const int m0 = blockIdx.x * 32;
    const int b  = m0 >> 13;
    const int n0 = m0 & 8191;
    const int tx = threadIdx.x & 31;
    const int ty = threadIdx.x >> 5;

    const float* p1 = points1 + (size_t)b * C1 * NPTS;
#pragma unroll
    for (int k = 0; k < 16; k++) {
        const int ch = ty + k * 8;
        tile[tx][ch] = p1[(size_t)ch * NPTS + n0 + tx];
    }
    __syncthreads();

    const int w = threadIdx.x >> 5, lane = threadIdx.x & 31;
    const float* p2t = d_P2T + (size_t)b * SPTS * C0;

#pragma unroll
    for (int k = 0; k < 4; k++) {
        const int pt = w * 4 + k;
        const int m  = m0 + pt;
        const uint4 nn = d_nn[m];
        const int i0 = nn.x & 0xFFFF, i1 = nn.x >> 16, i2 = nn.y;
        const float w0 = __uint_as_float(nn.z);
        const float w1 = __uint_as_float(nn.w);
        const float w2 = 1.f - w0 - w1;

        const float4* r0 = (const float4*)(p2t + (size_t)i0 * C0);
        const float4* r1 = (const float4*)(p2t + (size_t)i1 * C0);
        const float4* r2 = (const float4*)(p2t + (size_t)i2 * C0);

        uint4 H;
        {
            float4 a0 = r0[lane * 2],     c0 = r1[lane * 2],     e0 = r2[lane * 2];
            float4 a1 = r0[lane * 2 + 1], c1 = r1[lane * 2 + 1], e1 = r2[lane * 2 + 1];
            float v0 = fmaf(a0.x, w0, fmaf(c0.x, w1, e0.x * w2));
            float v1 = fmaf(a0.y, w0, fmaf(c0.y, w1, e0.y * w2));
            float v2 = fmaf(a0.z, w0, fmaf(c0.z, w1, e0.z * w2));
            float v3 = fmaf(a0.w, w0, fmaf(c0.w, w1, e0.w * w2));
            float v4 = fmaf(a1.x, w0, fmaf(c1.x, w1, e1.x * w2));
            float v5 = fmaf(a1.y, w0, fmaf(c1.y, w1, e1.y * w2));
            float v6 = fmaf(a1.z, w0, fmaf(c1.z, w1, e1.z * w2));
            float v7 = fmaf(a1.w, w0, fmaf(c1.w, w1, e1.w * w2));
            H.x = pack_h2(v0, v1);
            H.y = pack_h2(v2, v3);
            H.z = pack_h2(v4, v5);
            H.w = pack_h2(v6, v7);
        }
        __half* xh = d_Xh + (size_t)m * CIN;
        *(uint4*)(xh + lane * 8) = H;

        {
            float4 v = *(const float4*)(&tile[pt][lane * 4]);
            uint2 h;
            h.x = pack_h2(v.x, v.y);
            h.y = pack_h2(v.z, v.w);
            *(uint2*)(xh + C0 + lane * 4) = h;
        }
    }
}

// ---------------------------------------------------------------------------
// GEMM0 (mma.sync fp16): Y[m][o] = X[m][:].W0[o][:], K=384.
// ---------------------------------------------------------------------------
#define G0_STG  32768
#define G0_SMEM 69632

__global__ __launch_bounds__(256, 2)
void gemm0_kernel()
{
    extern __shared__ char smem[];
    const uint32_t sb = smem_u32(smem);
    const int tid = threadIdx.x;
    const int m0 = blockIdx.x * 128;
    const int ct = blockIdx.y;
    const int w = tid >> 5, lane = tid & 31;
    const int wm = w >> 2, wn = w & 3;
    const int lrow = lane & 15, lch = lane >> 4;

    float acc[4][4][4];
#pragma unroll
    for (int i = 0; i < 4; i++)
#pragma unroll
        for (int j = 0; j < 4; j++)
#pragma unroll
            for (int q = 0; q < 4; q++) acc[i][j][q] = 0.f;

    auto load_chunk = [&](int c, int stage) {
        const int k0 = c * 64;
        const uint32_t stg = sb + stage * G0_STG;
#pragma unroll
        for (int it = 0; it < 8; it++) {
            int u = it * 256 + tid;
            int arr = u >> 10;
            int v = u & 1023;
            int row = v >> 3, un = v & 7;
            uint32_t dst = stg + arr * 16384 + SW128(row * 128 + un * 16);
            const __half* src;
            if (arr == 0) src = d_W0h + (size_t)(ct * 128 + row) * CIN + k0 + un * 8;
            else          src = d_Xh  + (size_t)(m0 + row) * CIN + k0 + un * 8;
            cp_async16(dst, src);
        }
        CP_COMMIT();
    };

    load_chunk(0, 0);
    load_chunk(1, 1);

    for (int c = 0; c < 6; c++) {
        if (c < 5) asm volatile("cp.async.wait_group 1;" ::: "memory");
        else       asm volatile("cp.async.wait_group 0;" ::: "memory");
        __syncthreads();

        const uint32_t stg = sb + (c & 1) * G0_STG;
        const uint32_t aH = stg, bHb = stg + 16384;
#pragma unroll
        for (int kk = 0; kk < 4; kk++) {
            uint32_t Ah[4][4], Bh[4][2];
#pragma unroll
            for (int mf = 0; mf < 4; mf++) {
                uint32_t off = SW128((wm * 64 + mf * 16 + lrow) * 128 + (kk * 2 + lch) * 16);
                ldsm_x4(Ah[mf], aH + off);
            }
#pragma unroll
            for (int p = 0; p < 2; p++) {
                uint32_t off = SW128((wn * 32 + p * 16 + lrow) * 128 + (kk * 2 + lch) * 16);
                uint32_t r[4];
                ldsm_x4(r, bHb + off);
                Bh[2 * p][0] = r[0]; Bh[2 * p][1] = r[2];
                Bh[2 * p + 1][0] = r[1]; Bh[2 * p + 1][1] = r[3];
            }
#pragma unroll
            for (int mf = 0; mf < 4; mf++)
#pragma unroll
                for (int nf = 0; nf < 4; nf++)
                    mma_f16(acc[mf][nf], Ah[mf], Bh[nf]);
        }
        __syncthreads();
        if (c + 2 < 6) load_chunk(c + 2, c & 1);
    }

    // ---- fused BN0 stats (fp32, exact) ----
    float ssum[4][2] = {}, ssq[4][2] = {};
#pragma unroll
    for (int mf = 0; mf < 4; mf++)
#pragma unroll
        for (int nf = 0; nf < 4; nf++) {
            const float* a = acc[mf][nf];
            ssum[mf][0] += a[0] + a[1];
            ssum[mf][1] += a[2] + a[3];
            ssq[mf][0]  += a[0] * a[0] + a[1] * a[1];
            ssq[mf][1]  += a[2] * a[2] + a[3] * a[3];
        }
#pragma unroll
    for (int mf = 0; mf < 4; mf++)
#pragma unroll
        for (int h = 0; h < 2; h++) {
            float s = ssum[mf][h], q = ssq[mf][h];
            s += __shfl_xor_sync(0xffffffffu, s, 1);
            s += __shfl_xor_sync(0xffffffffu, s, 2);
            q += __shfl_xor_sync(0xffffffffu, q, 1);
            q += __shfl_xor_sync(0xffffffffu, q, 2);
            if ((lane & 3) == 0) {
                int ch = ct * 128 + wm * 64 + mf * 16 + (lane >> 2) + h * 8;
                atomicAdd(&d_stats[ch], s);
                atomicAdd(&d_stats[256 + ch], q);
            }
        }

    // ---- smem transpose -> coalesced fp16 d_Y [m][256] ----
    float* st = (float*)smem;
#pragma unroll
    for (int mf = 0; mf < 4; mf++)
#pragma unroll
        for (int nf = 0; nf < 4; nf++) {
            int ch = wm * 64 + mf * 16 + (lane >> 2);
            int pt = wn * 32 + nf * 8 + (lane & 3) * 2;
            st[pt * 132 + ch]           = acc[mf][nf][0];
            st[(pt + 1) * 132 + ch]     = acc[mf][nf][1];
            st[pt * 132 + ch + 8]       = acc[mf][nf][2];
            st[(pt + 1) * 132 + ch + 8] = acc[mf][nf][3];
        }
    __syncthreads();
    {
        const int row = tid >> 1, half = tid & 1;
        __half* dst = d_Y + (size_t)(m0 + row) * C0 + ct * 128 + half * 64;
        const float* sp = st + row * 132 + half * 64;
#pragma unroll
        for (int j = 0; j < 8; j++) {
            float4 a = *(const float4*)(sp + j * 8);
            float4 b = *(const float4*)(sp + j * 8 + 4);
            uint4 o;
            o.x = pack_h2(a.x, a.y);
            o.y = pack_h2(a.z, a.w);
            o.z = pack_h2(b.x, b.y);
            o.w = pack_h2(b.z, b.w);
            *(uint4*)(dst + j * 8) = o;
        }
    }
}

// ---------------------------------------------------------------------------
// GEMM1: Z = relu(aff0(Y)).W1^T, K=256. finalize0 fused into prologue.
// ---------------------------------------------------------------------------
#define G1_STG  32768
#define G1_SMEM (2048 + 2 * G1_STG)

__global__ __launch_bounds__(256, 2)
void gemm1_kernel(const float* __restrict__ g0, const float* __restrict__ be0)
{
    extern __shared__ char smem[];
    const uint32_t sb = smem_u32(smem);
    float* s_aff = (float*)smem;                 // 512 floats
    const int tid = threadIdx.x;
    const int m0 = blockIdx.x * 128;
    const int w = tid >> 5, lane = tid & 31;
    const int wm = w >> 2, wn = w & 3;
    const int lrow = lane & 15, lch = lane >> 4;

    // ---- fused finalize0: compute BN0 affine from global stats ----
    {
        const int c = tid;   // 256 threads = 256 channels
        const float mean = d_stats[c] * (1.f / MTOT);
        const float var  = d_stats[256 + c] * (1.f / MTOT) - mean * mean;
        const float sc   = g0[c] * rsqrtf(var + 1e-5f);
        s_aff[c]       = sc;
        s_aff[256 + c] = be0[c] - mean * sc;
    }
    __syncthreads();

    auto load_chunk = [&](int c, int stage) {
        const int k0 = c * 64;
        const uint32_t stg = sb + 2048 + stage * G1_STG;
#pragma unroll
        for (int it = 0; it < 4; it++) {
            int u = it * 256 + tid;
            int row = u >> 3, un = u & 7;
            uint32_t dst = stg + SW128(row * 128 + un * 16);
            const __half* src = d_W1h + (size_t)row * C0 + k0 + un * 8;
            cp_async16(dst, src);
        }
        CP_COMMIT();
        const uint32_t bB = stg + 16384;
        const int yrow = tid >> 1;
        const int koff = (tid & 1) * 32;
        const __half* yp = d_Y + (size_t)(m0 + yrow) * C0 + c * 64 + koff;
        const float* af  = s_aff + c * 64 + koff;
        const float* af2 = s_aff + 256 + c * 64 + koff;
        uint32_t hi[16];
#pragma unroll
        for (int i = 0; i < 32; i += 8) {
            uint4 raw = *(const uint4*)(yp + i);
            float2 f0 = __half22float2(*reinterpret_cast<__half2*>(&raw.x));
            float2 f1 = __half22float2(*reinterpret_cast<__half2*>(&raw.y));
            float2 f2 = __half22float2(*reinterpret_cast<__half2*>(&raw.z));
            float2 f3 = __half22float2(*reinterpret_cast<__half2*>(&raw.w));
            float x0 = fmaxf(fmaf(f0.x, af[i],     af2[i]),     0.f);
            float x1 = fmaxf(fmaf(f0.y, af[i + 1], af2[i + 1]), 0.f);
            float x2 = fmaxf(fmaf(f1.x, af[i + 2], af2[i + 2]), 0.f);
            float x3 = fmaxf(fmaf(f1.y, af[i + 3], af2[i + 3]), 0.f);
            float x4 = fmaxf(fmaf(f2.x, af[i + 4], af2[i + 4]), 0.f);
            float x5 = fmaxf(fmaf(f2.y, af[i + 5], af2[i + 5]), 0.f);
            float x6 = fmaxf(fmaf(f3.x, af[i + 6], af2[i + 6]), 0.f);
            float x7 = fmaxf(fmaf(f3.y, af[i + 7], af2[i + 7]), 0.f);
            hi[(i >> 1) + 0] = pack_h2(x0, x1);
            hi[(i >> 1) + 1] = pack_h2(x2, x3);
            hi[(i >> 1) + 2] = pack_h2(x4, x5);
            hi[(i >> 1) + 3] = pack_h2(x6, x7);
        }
#pragma unroll
        for (int uu = 0; uu < 4; uu++) {
            uint32_t off = SW128(yrow * 128 + ((tid & 1) * 4 + uu) * 16);
            asm volatile("st.shared.v4.b32 [%0], {%1,%2,%3,%4};"
                         :: "r"(bB + off), "r"(hi[uu * 4]), "r"(hi[uu * 4 + 1]),
                            "r"(hi[uu * 4 + 2]), "r"(hi[uu * 4 + 3]) : "memory");
        }
    };

    float acc[4][4][4];
#pragma unroll
    for (int i = 0; i < 4; i++)
#pragma unroll
        for (int j = 0; j < 4; j++)
#pragma unroll
            for (int q = 0; q < 4; q++) acc[i][j][q] = 0.f;

    load_chunk(0, 0);
    load_chunk(1, 1);

    for (int c = 0; c < 4; c++) {
        if (c < 3) asm volatile("cp.async.wait_group 1;" ::: "memory");
        else       asm volatile("cp.async.wait_group 0;" ::: "memory");
        __syncthreads();

        const uint32_t stg = sb + 2048 + (c & 1) * G1_STG;
        const uint32_t aH = stg, bHb = stg + 16384;
#pragma unroll
        for (int kk = 0; kk < 4; kk++) {
            uint32_t Ah[4][4], Bh[4][2];
#pragma unroll
            for (int mf = 0; mf < 4; mf++) {
                uint32_t off = SW128((wm * 64 + mf * 16 + lrow) * 128 + (kk * 2 + lch) * 16);
                ldsm_x4(Ah[mf], aH + off);
            }
#pragma unroll
            for (int p = 0; p < 2; p++) {
                uint32_t off = SW128((wn * 32 + p * 16 + lrow) * 128 + (kk * 2 + lch) * 16);
                uint32_t r[4];
                ldsm_x4(r, bHb + off);
                Bh[2 * p][0] = r[0]; Bh[2 * p][1] = r[2];
                Bh[2 * p + 1][0] = r[1]; Bh[2 * p + 1][1] = r[3];
            }
#pragma unroll
            for (int mf = 0; mf < 4; mf++)
#pragma unroll
                for (int nf = 0; nf < 4; nf++)
                    mma_f16(acc[mf][nf], Ah[mf], Bh[nf]);
        }
        __syncthreads();
        if (c + 2 < 4) load_chunk(c + 2, c & 1);
    }

    // ---- fused BN1 stats (fp32, exact) ----
    float ssum[4][2] = {}, ssq[4][2] = {};
#pragma unroll
    for (int mf = 0; mf < 4; mf++)
#pragma unroll
        for (int nf = 0; nf < 4; nf++) {
            const float* a = acc[mf][nf];
            ssum[mf][0] += a[0] + a[1];
            ssum[mf][1] += a[2] + a[3];
            ssq[mf][0]  += a[0] * a[0] + a[1] * a[1];
            ssq[mf][1]  += a[2] * a[2] + a[3] * a[3];
        }
#pragma unroll
    for (int mf = 0; mf < 4; mf++)
#pragma unroll
        for (int h = 0; h < 2; h++) {
            float s = ssum[mf][h], q = ssq[mf][h];
            s += __shfl_xor_sync(0xffffffffu, s, 1);
            s += __shfl_xor_sync(0xffffffffu, s, 2);
            q += __shfl_xor_sync(0xffffffffu, q, 1);
            q += __shfl_xor_sync(0xffffffffu, q, 2);
            if ((lane & 3) == 0) {
                int ch = wm * 64 + mf * 16 + (lane >> 2) + h * 8;
                atomicAdd(&d_stats[512 + ch], s);
                atomicAdd(&d_stats[640 + ch], q);
            }
        }

    // ---- store fp16 d_Z [c][m] ----
#pragma unroll
    for (int mf = 0; mf < 4; mf++)
#pragma unroll
        for (int nf = 0; nf < 4; nf++) {
            int ch = wm * 64 + mf * 16 + (lane >> 2);
            int pt = m0 + wn * 32 + nf * 8 + (lane & 3) * 2;
            *(uint32_t*)(d_Z + (size_t)ch * MTOT + pt) =
                pack_h2(acc[mf][nf][0], acc[mf][nf][1]);
            *(uint32_t*)(d_Z + (size_t)(ch + 8) * MTOT + pt) =
                pack_h2(acc[mf][nf][2], acc[mf][nf][3]);
        }
}

// ---------------------------------------------------------------------------
// output: finalize1 fused (per-channel BN constants from global stats) +
// affine + ReLU + [B,128,N] store. 8 elems/thread.
// ---------------------------------------------------------------------------
__global__ __launch_bounds__(256)
void output_kernel(float* __restrict__ out, const float* __restrict__ g1,
                   const float* __restrict__ be1)
{
    const int i = blockIdx.x * 256 + threadIdx.x;
    const int base = i * 8;
    const int o = base >> 16;
    const int m = base & 65535;
    const int b = m >> 13;
    const int n = m & 8191;
    // fused finalize1 (warp-uniform o -> broadcast loads)
    const float mean = d_stats[512 + o] * (1.f / MTOT);
    const float var  = d_stats[640 + o] * (1.f / MTOT) - mean * mean;
    const float sc   = g1[o] * rsqrtf(var + 1e-5f);
    const float sh   = be1[o] - mean * sc;

    uint4 raw = *(const uint4*)(d_Z + (size_t)o * MTOT + m);
    float2 f0 = __half22float2(*reinterpret_cast<__half2*>(&raw.x));
    float2 f1 = __half22float2(*reinterpret_cast<__half2*>(&raw.y));
    float2 f2 = __half22float2(*reinterpret_cast<__half2*>(&raw.z));
    float2 f3 = __half22float2(*reinterpret_cast<__half2*>(&raw.w));
    float4 v0, v1;
    v0.x = fmaxf(fmaf(f0.x, sc, sh), 0.f);
    v0.y = fmaxf(fmaf(f0.y, sc, sh), 0.f);
    v0.z = fmaxf(fmaf(f1.x, sc, sh), 0.f);
    v0.w = fmaxf(fmaf(f1.y, sc, sh), 0.f);
    v1.x = fmaxf(fmaf(f2.x, sc, sh), 0.f);
    v1.y = fmaxf(fmaf(f2.y, sc, sh), 0.f);
    v1.z = fmaxf(fmaf(f3.x, sc, sh), 0.f);
    v1.w = fmaxf(fmaf(f3.y, sc, sh), 0.f);
    float* dst = out + ((size_t)b * C1 + o) * NPTS + n;
    *(float4*)(dst)     = v0;
    *(float4*)(dst + 4) = v1;
}

// ---------------------------------------------------------------------------
extern "C" void kernel_launch(void* const* d_in, const int* in_sizes, int n_in,
                              void* d_out, int out_size)
{
    const float* xyz1    = (const float*)d_in[0];
    const float* xyz2    = (const float*)d_in[1];
    const float* points1 = (const float*)d_in[2];
    const float* points2 = (const float*)d_in[3];
    const float* w0      = (const float*)d_in[4];
    const float* g0      = (const float*)d_in[6];
    const float* be0     = (const float*)d_in[7];
    const float* w1      = (const float*)d_in[8];
    const float* g1      = (const float*)d_in[10];
    const float* be1     = (const float*)d_in[11];
    float* out = (float*)d_out;

    cudaFuncSetAttribute(gemm0_kernel, cudaFuncAttributeMaxDynamicSharedMemorySize, G0_SMEM);
    cudaFuncSetAttribute(gemm1_kernel, cudaFuncAttributeMaxDynamicSharedMemorySize, G1_SMEM);

    prep_kernel<<<1088, 256>>>(xyz1, xyz2, points2, w0, w1);   // (1)
    fused_x_kernel<<<MTOT / 32, 256>>>(points1);               // (2)
    gemm0_kernel<<<dim3(MTOT / 128, 2), 256, G0_SMEM>>>();     // (3)
    gemm1_kernel<<<MTOT / 128, 256, G1_SMEM>>>(g0, be0);       // (4) <- profiled
    output_kernel<<<(C1 * MTOT / 8) / 256, 256>>>(out, g1, be1); // (5)
}

// round 14
// speedup vs baseline: 1.5550x; 1.5550x over previous
#include <cuda_runtime.h>
#include <cuda_fp16.h>
#include <cstdint>

#define BATCH 8
#define NPTS  8192
#define SPTS  2048
#define MTOT  65536
#define CIN   384
#define C0    256
#define C1    128

// ------------------------- device scratch -------------------------
__device__ __half d_Xh[(size_t)MTOT * CIN];          // [m][384] fp16, k-contiguous
__device__ __half d_Y[(size_t)MTOT * C0];            // [m][256] fp16 (raw conv0 out)
__device__ __half d_Z[(size_t)C1 * MTOT];            // [c][m]   fp16 (raw conv1 out)
__device__ __half d_P2T[(size_t)BATCH * SPTS * C0];  // [b][s][256] fp16
__device__ __half d_W0h[C0 * CIN];                   // [256][384]
__device__ __half d_W1h[C1 * C0];                    // [128][256]
__device__ uint4  d_nn[MTOT];
__device__ float  d_stats[768];                      // sum0,sq0 | sum1,sq1
__device__ float  d_aff[768];                        // sc0,sh0  | sc1,sh1

// ------------------------- helpers -------------------------
__device__ __forceinline__ uint32_t smem_u32(const void* p) {
    uint32_t a;
    asm("{ .reg .u64 t; cvta.to.shared.u64 t, %1; cvt.u32.u64 %0, t; }" : "=r"(a) : "l"(p));
    return a;
}
#define SW128(o) ((o) ^ (((o) >> 3) & 0x70))
#define CP_COMMIT() asm volatile("cp.async.commit_group;" ::: "memory")

__device__ __forceinline__ void cp_async16(uint32_t dst, const void* src) {
    size_t g = __cvta_generic_to_global(src);
    asm volatile("cp.async.cg.shared.global [%0], [%1], 16;" :: "r"(dst), "l"(g));
}
__device__ __forceinline__ void ldsm_x4(uint32_t (&r)[4], uint32_t addr) {
    asm volatile("ldmatrix.sync.aligned.m8n8.x4.shared.b16 {%0,%1,%2,%3}, [%4];"
                 : "=r"(r[0]), "=r"(r[1]), "=r"(r[2]), "=r"(r[3]) : "r"(addr));
}
__device__ __forceinline__ void mma_f16(float (&c)[4], const uint32_t (&a)[4],
                                        const uint32_t (&b)[2]) {
    asm volatile(
        "mma.sync.aligned.m16n8k16.row.col.f32.f16.f16.f32 "
        "{%0,%1,%2,%3}, {%4,%5,%6,%7}, {%8,%9}, {%0,%1,%2,%3};"
        : "+f"(c[0]), "+f"(c[1]), "+f"(c[2]), "+f"(c[3])
        : "r"(a[0]), "r"(a[1]), "r"(a[2]), "r"(a[3]), "r"(b[0]), "r"(b[1]));
}
__device__ __forceinline__ uint32_t pack_h2(float v0, float v1) {
    __half2 h = __floats2half2_rn(v0, v1);
    return *reinterpret_cast<uint32_t*>(&h);
}

// ---------------------------------------------------------------------------
// split_w: W0+W1 -> fp16 (+ stats zero in block 0)
// ---------------------------------------------------------------------------
__global__ __launch_bounds__(256)
void split_w_kernel(const float* __restrict__ w0, const float* __restrict__ w1)
{
    if (blockIdx.x == 0)
        for (int i = threadIdx.x; i < 768; i += 256) d_stats[i] = 0.f;
    int i = blockIdx.x * 256 + threadIdx.x;
    if (i < C0 * CIN) d_W0h[i] = __float2half_rn(w0[i]);
    int j = i - C0 * CIN;
    if (j >= 0 && j < C1 * C0) d_W1h[j] = __float2half_rn(w1[j]);
}

// ---------------------------------------------------------------------------
// prep: blocks [0,128) = 3-NN search (2 pts/thread); blocks [128,640) =
// points2 transpose -> d_P2T [b][s][256] fp16.
// ---------------------------------------------------------------------------
__global__ __launch_bounds__(256)
void prep_kernel(const float* __restrict__ xyz1, const float* __restrict__ xyz2,
                 const float* __restrict__ points2)
{
    __shared__ __align__(16) char shmem[33280];

    if (blockIdx.x < 128) {
        float4* sp = (float4*)shmem;
        const int bx = blockIdx.x & 15;
        const int b  = blockIdx.x >> 4;
        const int t  = threadIdx.x;

        const float* x2 = xyz2 + (size_t)b * 3 * SPTS;
        for (int s = t; s < SPTS; s += 256) {
            float x = x2[s], y = x2[SPTS + s], z = x2[2 * SPTS + s];
            sp[s] = make_float4(-2.f * x, -2.f * y, -2.f * z, x * x + y * y + z * z);
        }
        __syncthreads();

        const int nA = bx * 512 + t;
        const int nB = nA + 256;
        const float* x1 = xyz1 + (size_t)b * 3 * NPTS;
        const float ax = x1[nA], ay = x1[NPTS + nA], az = x1[2 * NPTS + nA];
        const float bx2 = x1[nB], by = x1[NPTS + nB], bz = x1[2 * NPTS + nB];

        float a0 = 3.4e38f, a1 = 3.4e38f, a2 = 3.4e38f;
        float b0 = 3.4e38f, b1 = 3.4e38f, b2 = 3.4e38f;
        int ai0 = 0, ai1 = 0, ai2 = 0, bi0 = 0, bi1 = 0, bi2 = 0;

#pragma unroll 4
        for (int s = 0; s < SPTS; ++s) {
            float4 p = sp[s];
            float ka = fmaf(p.x, ax, fmaf(p.y, ay, fmaf(p.z, az, p.w)));
            float kb = fmaf(p.x, bx2, fmaf(p.y, by, fmaf(p.z, bz, p.w)));
            if (ka < a2) {
                if (ka < a1) {
                    a2 = a1; ai2 = ai1;
                    if (ka < a0) { a1 = a0; ai1 = ai0; a0 = ka; ai0 = s; }
                    else         { a1 = ka; ai1 = s; }
                } else { a2 = ka; ai2 = s; }
            }
            if (kb < b2) {
                if (kb < b1) {
                    b2 = b1; bi2 = bi1;
                    if (kb < b0) { b1 = b0; bi1 = bi0; b0 = kb; bi0 = s; }
                    else         { b1 = kb; bi1 = s; }
                } else { b2 = kb; bi2 = s; }
            }
        }

        {
            const float sn = ax * ax + ay * ay + az * az;
            float r0 = 1.f / (a0 + sn + 1e-8f), r1 = 1.f / (a1 + sn + 1e-8f),
                  r2 = 1.f / (a2 + sn + 1e-8f);
            float ws = r0 + r1 + r2;
            uint4 o;
            o.x = (uint32_t)ai0 | ((uint32_t)ai1 << 16);
            o.y = (uint32_t)ai2;
            o.z = __float_as_uint(r0 / ws);
            o.w = __float_as_uint(r1 / ws);
            d_nn[b * NPTS + nA] = o;
        }
        {
            const float sn = bx2 * bx2 + by * by + bz * bz;
            float r0 = 1.f / (b0 + sn + 1e-8f), r1 = 1.f / (b1 + sn + 1e-8f),
                  r2 = 1.f / (b2 + sn + 1e-8f);
            float ws = r0 + r1 + r2;
            uint4 o;
            o.x = (uint32_t)bi0 | ((uint32_t)bi1 << 16);
            o.y = (uint32_t)bi2;
            o.z = __float_as_uint(r0 / ws);
            o.w = __float_as_uint(r1 / ws);
            d_nn[b * NPTS + nB] = o;
        }
    } else {
        float (*tile)[260] = (float(*)[260])shmem;
        const int tb = blockIdx.x - 128;
        const int b  = tb >> 6;
        const int s0 = (tb & 63) * 32;
        const int tx = threadIdx.x & 31;
        const int ty = threadIdx.x >> 5;

        const float* src = points2 + (size_t)b * C0 * SPTS;
#pragma unroll
        for (int k = 0; k < 32; k++) {
            const int ch = ty + k * 8;
            tile[tx][ch] = src[(size_t)ch * SPTS + s0 + tx];
        }
        __syncthreads();

        // warp w writes s-rows w,w+8,w+16,w+24 as fp16: lane packs 8 ch = 16B
        const int w = threadIdx.x >> 5, lane = threadIdx.x & 31;
#pragma unroll
        for (int k = 0; k < 4; k++) {
            const int s = w + k * 8;
            __half* dst = d_P2T + ((size_t)b * SPTS + s0 + s) * C0;
            const float* sp2 = &tile[s][lane * 8];
            uint4 o;
            o.x = pack_h2(sp2[0], sp2[1]);
            o.y = pack_h2(sp2[2], sp2[3]);
            o.z = pack_h2(sp2[4], sp2[5]);
            o.w = pack_h2(sp2[6], sp2[7]);
            *(uint4*)(dst + lane * 8) = o;
        }
    }
}

// ---------------------------------------------------------------------------
// Fused X-builder: warp-per-point; fp16 P2T gathers (one uint4/lane/row).
// ---------------------------------------------------------------------------
__global__ __launch_bounds__(256)
void fused_x_kernel(const float* __restrict__ points1)
{
    __shared__ float tile[32][132];
    const int m0 = blockIdx.x * 32;
    const int b  = m0 >> 13;
    const int n0 = m0 & 8191;
    const int tx = threadIdx.x & 31;
    const int ty = threadIdx.x >> 5;

    const float* p1 = points1 + (size_t)b * C1 * NPTS;
#pragma unroll
    for (int k = 0; k < 16; k++) {
        const int ch = ty + k * 8;
        tile[tx][ch] = p1[(size_t)ch * NPTS + n0 + tx];
    }
    __syncthreads();

    const int w = threadIdx.x >> 5, lane = threadIdx.x & 31;
    const __half* p2t = d_P2T + (size_t)b * SPTS * C0;

#pragma unroll
    for (int k = 0; k < 4; k++) {
        const int pt = w * 4 + k;
        const int m  = m0 + pt;
        const uint4 nn = d_nn[m];
        const int i0 = nn.x & 0xFFFF, i1 = nn.x >> 16, i2 = nn.y;
        const float w0 = __uint_as_float(nn.z);
        const float w1 = __uint_as_float(nn.w);
        const float w2 = 1.f - w0 - w1;

        uint4 ra = *(const uint4*)(p2t + (size_t)i0 * C0 + lane * 8);
        uint4 rc = *(const uint4*)(p2t + (size_t)i1 * C0 + lane * 8);
        uint4 re = *(const uint4*)(p2t + (size_t)i2 * C0 + lane * 8);

        uint4 H;
        {
            const __half2* ha = (const __half2*)&ra;
            const __half2* hc = (const __half2*)&rc;
            const __half2* he = (const __half2*)&re;
#pragma unroll
            for (int j = 0; j < 4; j++) {
                float2 fa = __half22float2(ha[j]);
                float2 fc = __half22float2(hc[j]);
                float2 fe = __half22float2(he[j]);
                float v0 = fmaf(fa.x, w0, fmaf(fc.x, w1, fe.x * w2));
                float v1 = fmaf(fa.y, w0, fmaf(fc.y, w1, fe.y * w2));
                (&H.x)[j] = pack_h2(v0, v1);
            }
        }
        __half* xh = d_Xh + (size_t)m * CIN;
        *(uint4*)(xh + lane * 8) = H;

        {
            float4 v = *(const float4*)(&tile[pt][lane * 4]);
            uint2 h;
            h.x = pack_h2(v.x, v.y);
            h.y = pack_h2(v.z, v.w);
            *(uint2*)(xh + C0 + lane * 4) = h;
        }
    }
}

// ---------------------------------------------------------------------------
// GEMM0 (mma.sync fp16): Y[m][o] = X[m][:].W0[o][:], K=384.
// 2-stage cp.async (32KB/stage), 2 CTAs/SM. fp32 stats + fp16 Y store.
// ---------------------------------------------------------------------------
#define G0_STG  32768
#define G0_SMEM 69632

__global__ __launch_bounds__(256, 2)
void gemm0_kernel()
{
    extern __shared__ char smem[];
    const uint32_t sb = smem_u32(smem);
    const int tid = threadIdx.x;
    const int m0 = blockIdx.x * 128;
    const int ct = blockIdx.y;
    const int w = tid >> 5, lane = tid & 31;
    const int wm = w >> 2, wn = w & 3;
    const int lrow = lane & 15, lch = lane >> 4;

    float acc[4][4][4];
#pragma unroll
    for (int i = 0; i < 4; i++)
#pragma unroll
        for (int j = 0; j < 4; j++)
#pragma unroll
            for (int q = 0; q < 4; q++) acc[i][j][q] = 0.f;

    auto load_chunk = [&](int c, int stage) {
        const int k0 = c * 64;
        const uint32_t stg = sb + stage * G0_STG;
#pragma unroll
        for (int it = 0; it < 8; it++) {
            int u = it * 256 + tid;
            int arr = u >> 10;
            int v = u & 1023;
            int row = v >> 3, un = v & 7;
            uint32_t dst = stg + arr * 16384 + SW128(row * 128 + un * 16);
            const __half* src;
            if (arr == 0) src = d_W0h + (size_t)(ct * 128 + row) * CIN + k0 + un * 8;
            else          src = d_Xh  + (size_t)(m0 + row) * CIN + k0 + un * 8;
            cp_async16(dst, src);
        }
        CP_COMMIT();
    };

    load_chunk(0, 0);
    load_chunk(1, 1);

    for (int c = 0; c < 6; c++) {
        if (c < 5) asm volatile("cp.async.wait_group 1;" ::: "memory");
        else       asm volatile("cp.async.wait_group 0;" ::: "memory");
        __syncthreads();

        const uint32_t stg = sb + (c & 1) * G0_STG;
        const uint32_t aH = stg, bHb = stg + 16384;
#pragma unroll
        for (int kk = 0; kk < 4; kk++) {
            uint32_t Ah[4][4], Bh[4][2];
#pragma unroll
            for (int mf = 0; mf < 4; mf++) {
                uint32_t off = SW128((wm * 64 + mf * 16 + lrow) * 128 + (kk * 2 + lch) * 16);
                ldsm_x4(Ah[mf], aH + off);
            }
#pragma unroll
            for (int p = 0; p < 2; p++) {
                uint32_t off = SW128((wn * 32 + p * 16 + lrow) * 128 + (kk * 2 + lch) * 16);
                uint32_t r[4];
                ldsm_x4(r, bHb + off);
                Bh[2 * p][0] = r[0]; Bh[2 * p][1] = r[2];
                Bh[2 * p + 1][0] = r[1]; Bh[2 * p + 1][1] = r[3];
            }
#pragma unroll
            for (int mf = 0; mf < 4; mf++)
#pragma unroll
                for (int nf = 0; nf < 4; nf++)
                    mma_f16(acc[mf][nf], Ah[mf], Bh[nf]);
        }
        __syncthreads();
        if (c + 2 < 6) load_chunk(c + 2, c & 1);
    }

    // ---- fused BN0 stats (fp32, exact) ----
    float ssum[4][2] = {}, ssq[4][2] = {};
#pragma unroll
    for (int mf = 0; mf < 4; mf++)
#pragma unroll
        for (int nf = 0; nf < 4; nf++) {
            const float* a = acc[mf][nf];
            ssum[mf][0] += a[0] + a[1];
            ssum[mf][1] += a[2] + a[3];
            ssq[mf][0]  += a[0] * a[0] + a[1] * a[1];
            ssq[mf][1]  += a[2] * a[2] + a[3] * a[3];
        }
#pragma unroll
    for (int mf = 0; mf < 4; mf++)
#pragma unroll
        for (int h = 0; h < 2; h++) {
            float s = ssum[mf][h], q = ssq[mf][h];
            s += __shfl_xor_sync(0xffffffffu, s, 1);
            s += __shfl_xor_sync(0xffffffffu, s, 2);
            q += __shfl_xor_sync(0xffffffffu, q, 1);
            q += __shfl_xor_sync(0xffffffffu, q, 2);
            if ((lane & 3) == 0) {
                int ch = ct * 128 + wm * 64 + mf * 16 + (lane >> 2) + h * 8;
                atomicAdd(&d_stats[ch], s);
                atomicAdd(&d_stats[256 + ch], q);
            }
        }

    // ---- smem transpose -> coalesced fp16 d_Y [m][256] ----
    float* st = (float*)smem;
#pragma unroll
    for (int mf = 0; mf < 4; mf++)
#pragma unroll
        for (int nf = 0; nf < 4; nf++) {
            int ch = wm * 64 + mf * 16 + (lane >> 2);
            int pt = wn * 32 + nf * 8 + (lane & 3) * 2;
            st[pt * 132 + ch]           = acc[mf][nf][0];
            st[(pt + 1) * 132 + ch]     = acc[mf][nf][1];
            st[pt * 132 + ch + 8]       = acc[mf][nf][2];
            st[(pt + 1) * 132 + ch + 8] = acc[mf][nf][3];
        }
    __syncthreads();
    {
        const int row = tid >> 1, half = tid & 1;
        __half* dst = d_Y + (size_t)(m0 + row) * C0 + ct * 128 + half * 64;
        const float* sp = st + row * 132 + half * 64;
#pragma unroll
        for (int j = 0; j < 8; j++) {
            float4 a = *(const float4*)(sp + j * 8);
            float4 b = *(const float4*)(sp + j * 8 + 4);
            uint4 o;
            o.x = pack_h2(a.x, a.y);
            o.y = pack_h2(a.z, a.w);
            o.z = pack_h2(b.x, b.y);
            o.w = pack_h2(b.z, b.w);
            *(uint4*)(dst + j * 8) = o;
        }
    }
}

// ---------------------------------------------------------------------------
// finalize BN constants (conv biases cancel under training-mode BN)
// ---------------------------------------------------------------------------
template<int LAYER>
__global__ void finalize_kernel(const float* __restrict__ g, const float* __restrict__ be)
{
    const int c  = threadIdx.x;
    const int o  = LAYER ? 512 : 0;
    const int cc = LAYER ? C1 : C0;
    const float mean = d_stats[o + c] * (1.f / MTOT);
    const float var  = d_stats[o + cc + c] * (1.f / MTOT) - mean * mean;
    const float sc   = g[c] * rsqrtf(var + 1e-5f);
    d_aff[o + c]      = sc;
    d_aff[o + cc + c] = be[c] - mean * sc;
}

// ---------------------------------------------------------------------------
// GEMM1: Z = relu(aff0(Y)) . W1^T, K=256, fp16 in/out. 2-stage 32KB.
// ---------------------------------------------------------------------------
#define G1_STG  32768
#define G1_SMEM (2048 + 2 * G1_STG)

__global__ __launch_bounds__(256, 2)
void gemm1_kernel()
{
    extern __shared__ char smem[];
    const uint32_t sb = smem_u32(smem);
    float* s_aff = (float*)smem;                 // 512 floats
    const int tid = threadIdx.x;
    const int m0 = blockIdx.x * 128;
    const int w = tid >> 5, lane = tid & 31;
    const int wm = w >> 2, wn = w & 3;
    const int lrow = lane & 15, lch = lane >> 4;

    for (int i = tid; i < 512; i += 256) s_aff[i] = d_aff[i];
    __syncthreads();

    auto load_chunk = [&](int c, int stage) {
        const int k0 = c * 64;
        const uint32_t stg = sb + 2048 + stage * G1_STG;
#pragma unroll
        for (int it = 0; it < 4; it++) {
            int u = it * 256 + tid;
            int row = u >> 3, un = u & 7;
            uint32_t dst = stg + SW128(row * 128 + un * 16);
            const __half* src = d_W1h + (size_t)row * C0 + k0 + un * 8;
            cp_async16(dst, src);
        }
        CP_COMMIT();
        const uint32_t bB = stg + 16384;
        const int yrow = tid >> 1;
        const int koff = (tid & 1) * 32;
        const __half* yp = d_Y + (size_t)(m0 + yrow) * C0 + c * 64 + koff;
        const float* af  = s_aff + c * 64 + koff;
        const float* af2 = s_aff + 256 + c * 64 + koff;
        uint32_t hi[16];
#pragma unroll
        for (int i = 0; i < 32; i += 8) {
            uint4 raw = *(const uint4*)(yp + i);
            float2 f0 = __half22float2(*reinterpret_cast<__half2*>(&raw.x));
            float2 f1 = __half22float2(*reinterpret_cast<__half2*>(&raw.y));
            float2 f2 = __half22float2(*reinterpret_cast<__half2*>(&raw.z));
            float2 f3 = __half22float2(*reinterpret_cast<__half2*>(&raw.w));
            float x0 = fmaxf(fmaf(f0.x, af[i],     af2[i]),     0.f);
            float x1 = fmaxf(fmaf(f0.y, af[i + 1], af2[i + 1]), 0.f);
            float x2 = fmaxf(fmaf(f1.x, af[i + 2], af2[i + 2]), 0.f);
            float x3 = fmaxf(fmaf(f1.y, af[i + 3], af2[i + 3]), 0.f);
            float x4 = fmaxf(fmaf(f2.x, af[i + 4], af2[i + 4]), 0.f);
            float x5 = fmaxf(fmaf(f2.y, af[i + 5], af2[i + 5]), 0.f);
            float x6 = fmaxf(fmaf(f3.x, af[i + 6], af2[i + 6]), 0.f);
            float x7 = fmaxf(fmaf(f3.y, af[i + 7], af2[i + 7]), 0.f);
            hi[(i >> 1) + 0] = pack_h2(x0, x1);
            hi[(i >> 1) + 1] = pack_h2(x2, x3);
            hi[(i >> 1) + 2] = pack_h2(x4, x5);
            hi[(i >> 1) + 3] = pack_h2(x6, x7);
        }
#pragma unroll
        for (int uu = 0; uu < 4; uu++) {
            uint32_t off = SW128(yrow * 128 + ((tid & 1) * 4 + uu) * 16);
            asm volatile("st.shared.v4.b32 [%0], {%1,%2,%3,%4};"
                         :: "r"(bB + off), "r"(hi[uu * 4]), "r"(hi[uu * 4 + 1]),
                            "r"(hi[uu * 4 + 2]), "r"(hi[uu * 4 + 3]) : "memory");
        }
    };

    float acc[4][4][4];
#pragma unroll
    for (int i = 0; i < 4; i++)
#pragma unroll
        for (int j = 0; j < 4; j++)
#pragma unroll
            for (int q = 0; q < 4; q++) acc[i][j][q] = 0.f;

    load_chunk(0, 0);
    load_chunk(1, 1);

    for (int c = 0; c < 4; c++) {
        if (c < 3) asm volatile("cp.async.wait_group 1;" ::: "memory");
        else       asm volatile("cp.async.wait_group 0;" ::: "memory");
        __syncthreads();

        const uint32_t stg = sb + 2048 + (c & 1) * G1_STG;
        const uint32_t aH = stg, bHb = stg + 16384;
#pragma unroll
        for (int kk = 0; kk < 4; kk++) {
            uint32_t Ah[4][4], Bh[4][2];
#pragma unroll
            for (int mf = 0; mf < 4; mf++) {
                uint32_t off = SW128((wm * 64 + mf * 16 + lrow) * 128 + (kk * 2 + lch) * 16);
                ldsm_x4(Ah[mf], aH + off);
            }
#pragma unroll
            for (int p = 0; p < 2; p++) {
                uint32_t off = SW128((wn * 32 + p * 16 + lrow) * 128 + (kk * 2 + lch) * 16);
                uint32_t r[4];
                ldsm_x4(r, bHb + off);
                Bh[2 * p][0] = r[0]; Bh[2 * p][1] = r[2];
                Bh[2 * p + 1][0] = r[1]; Bh[2 * p + 1][1] = r[3];
            }
#pragma unroll
            for (int mf = 0; mf < 4; mf++)
#pragma unroll
                for (int nf = 0; nf < 4; nf++)
                    mma_f16(acc[mf][nf], Ah[mf], Bh[nf]);
        }
        __syncthreads();
        if (c + 2 < 4) load_chunk(c + 2, c & 1);
    }

    // ---- fused BN1 stats (fp32, exact) ----
    float ssum[4][2] = {}, ssq[4][2] = {};
#pragma unroll
    for (int mf = 0; mf < 4; mf++)
#pragma unroll
        for (int nf = 0; nf < 4; nf++) {
            const float* a = acc[mf][nf];
            ssum[mf][0] += a[0] + a[1];
            ssum[mf][1] += a[2] + a[3];
            ssq[mf][0]  += a[0] * a[0] + a[1] * a[1];
            ssq[mf][1]  += a[2] * a[2] + a[3] * a[3];
        }
#pragma unroll
    for (int mf = 0; mf < 4; mf++)
#pragma unroll
        for (int h = 0; h < 2; h++) {
            float s = ssum[mf][h], q = ssq[mf][h];
            s += __shfl_xor_sync(0xffffffffu, s, 1);
            s += __shfl_xor_sync(0xffffffffu, s, 2);
            q += __shfl_xor_sync(0xffffffffu, q, 1);
            q += __shfl_xor_sync(0xffffffffu, q, 2);
            if ((lane & 3) == 0) {
                int ch = wm * 64 + mf * 16 + (lane >> 2) + h * 8;
                atomicAdd(&d_stats[512 + ch], s);
                atomicAdd(&d_stats[640 + ch], q);
            }
        }

    // ---- store fp16 d_Z [c][m] ----
#pragma unroll
    for (int mf = 0; mf < 4; mf++)
#pragma unroll
        for (int nf = 0; nf < 4; nf++) {
            int ch = wm * 64 + mf * 16 + (lane >> 2);
            int pt = m0 + wn * 32 + nf * 8 + (lane & 3) * 2;
            *(uint32_t*)(d_Z + (size_t)ch * MTOT + pt) =
                pack_h2(acc[mf][nf][0], acc[mf][nf][1]);
            *(uint32_t*)(d_Z + (size_t)(ch + 8) * MTOT + pt) =
                pack_h2(acc[mf][nf][2], acc[mf][nf][3]);
        }
}

// ---------------------------------------------------------------------------
// BN1 affine + ReLU + output [B,128,N]; fp16 Z in, fp32 out. 8 elems/thread.
// ---------------------------------------------------------------------------
__global__ __launch_bounds__(256)
void output_kernel(float* __restrict__ out)
{
    const int i = blockIdx.x * 256 + threadIdx.x;
    const int base = i * 8;
    const int o = base >> 16;
    const int m = base & 65535;
    const int b = m >> 13;
    const int n = m & 8191;
    uint4 raw = *(const uint4*)(d_Z + (size_t)o * MTOT + m);
    const float sc = d_aff[512 + o];
    const float sh = d_aff[640 + o];
    float2 f0 = __half22float2(*reinterpret_cast<__half2*>(&raw.x));
    float2 f1 = __half22float2(*reinterpret_cast<__half2*>(&raw.y));
    float2 f2 = __half22float2(*reinterpret_cast<__half2*>(&raw.z));
    float2 f3 = __half22float2(*reinterpret_cast<__half2*>(&raw.w));
    float4 v0, v1;
    v0.x = fmaxf(fmaf(f0.x, sc, sh), 0.f);
    v0.y = fmaxf(fmaf(f0.y, sc, sh), 0.f);
    v0.z = fmaxf(fmaf(f1.x, sc, sh), 0.f);
    v0.w = fmaxf(fmaf(f1.y, sc, sh), 0.f);
    v1.x = fmaxf(fmaf(f2.x, sc, sh), 0.f);
    v1.y = fmaxf(fmaf(f2.y, sc, sh), 0.f);
    v1.z = fmaxf(fmaf(f3.x, sc, sh), 0.f);
    v1.w = fmaxf(fmaf(f3.y, sc, sh), 0.f);
    float* dst = out + ((size_t)b * C1 + o) * NPTS + n;
    *(float4*)(dst)     = v0;
    *(float4*)(dst + 4) = v1;
}

// ---------------------------------------------------------------------------
extern "C" void kernel_launch(void* const* d_in, const int* in_sizes, int n_in,
                              void* d_out, int out_size)
{
    const float* xyz1    = (const float*)d_in[0];
    const float* xyz2    = (const float*)d_in[1];
    const float* points1 = (const float*)d_in[2];
    const float* points2 = (const float*)d_in[3];
    const float* w0      = (const float*)d_in[4];
    const float* g0      = (const float*)d_in[6];
    const float* be0     = (const float*)d_in[7];
    const float* w1      = (const float*)d_in[8];
    const float* g1      = (const float*)d_in[10];
    const float* be1     = (const float*)d_in[11];
    float* out = (float*)d_out;

    cudaFuncSetAttribute(gemm0_kernel, cudaFuncAttributeMaxDynamicSharedMemorySize, G0_SMEM);
    cudaFuncSetAttribute(gemm1_kernel, cudaFuncAttributeMaxDynamicSharedMemorySize, G1_SMEM);

    prep_kernel<<<640, 256>>>(xyz1, xyz2, points2);                      // (1)
    split_w_kernel<<<(C0 * CIN + C1 * C0 + 255) / 256, 256>>>(w0, w1);   // (2)
    fused_x_kernel<<<MTOT / 32, 256>>>(points1);                         // (3)

    gemm0_kernel<<<dim3(MTOT / 128, 2), 256, G0_SMEM>>>();               // (4) <- profiled
    finalize_kernel<0><<<1, C0>>>(g0, be0);                              // (5)

    gemm1_kernel<<<MTOT / 128, 256, G1_SMEM>>>();                        // (6)
    finalize_kernel<1><<<1, C1>>>(g1, be1);                              // (7)

    output_kernel<<<(C1 * MTOT / 8) / 256, 256>>>(out);                  // (8)
}

// round 15
// speedup vs baseline: 1.5998x; 1.0288x over previous
#include <cuda_runtime.h>
#include <cuda_fp16.h>
#include <cstdint>

#define BATCH 8
#define NPTS  8192
#define SPTS  2048
#define MTOT  65536
#define CIN   384
#define C0    256
#define C1    128

// ------------------------- device scratch -------------------------
__device__ __half d_Xh[(size_t)MTOT * CIN];          // [m][384] fp16, k-contiguous
__device__ __half d_Y[(size_t)MTOT * C0];            // [m][256] fp16 (raw conv0 out)
__device__ __half d_Z[(size_t)C1 * MTOT];            // [c][m]   fp16 (raw conv1 out)
__device__ __half d_P2T[(size_t)BATCH * SPTS * C0];  // [b][s][256] fp16
__device__ __half d_W0h[C0 * CIN];                   // [256][384]
__device__ __half d_W1h[C1 * C0];                    // [128][256]
__device__ uint4  d_nn[MTOT];
__device__ float  d_stats[768];                      // sum0,sq0 | sum1,sq1

// ------------------------- helpers -------------------------
__device__ __forceinline__ uint32_t smem_u32(const void* p) {
    uint32_t a;
    asm("{ .reg .u64 t; cvta.to.shared.u64 t, %1; cvt.u32.u64 %0, t; }" : "=r"(a) : "l"(p));
    return a;
}
#define SW128(o) ((o) ^ (((o) >> 3) & 0x70))
#define CP_COMMIT() asm volatile("cp.async.commit_group;" ::: "memory")

__device__ __forceinline__ void cp_async16(uint32_t dst, const void* src) {
    size_t g = __cvta_generic_to_global(src);
    asm volatile("cp.async.cg.shared.global [%0], [%1], 16;" :: "r"(dst), "l"(g));
}
__device__ __forceinline__ void ldsm_x4(uint32_t (&r)[4], uint32_t addr) {
    asm volatile("ldmatrix.sync.aligned.m8n8.x4.shared.b16 {%0,%1,%2,%3}, [%4];"
                 : "=r"(r[0]), "=r"(r[1]), "=r"(r[2]), "=r"(r[3]) : "r"(addr));
}
__device__ __forceinline__ void mma_f16(float (&c)[4], const uint32_t (&a)[4],
                                        const uint32_t (&b)[2]) {
    asm volatile(
        "mma.sync.aligned.m16n8k16.row.col.f32.f16.f16.f32 "
        "{%0,%1,%2,%3}, {%4,%5,%6,%7}, {%8,%9}, {%0,%1,%2,%3};"
        : "+f"(c[0]), "+f"(c[1]), "+f"(c[2]), "+f"(c[3])
        : "r"(a[0]), "r"(a[1]), "r"(a[2]), "r"(a[3]), "r"(b[0]), "r"(b[1]));
}
__device__ __forceinline__ uint32_t pack_h2(float v0, float v1) {
    __half2 h = __floats2half2_rn(v0, v1);
    return *reinterpret_cast<uint32_t*>(&h);
}

// ---------------------------------------------------------------------------
// prep: [0,128) 3-NN (2 pts/thread, identical to R14) | [128,640) points2
// transpose -> fp16 P2T | [640,1152) W0/W1 -> fp16 (+ stats zero).
// ---------------------------------------------------------------------------
__global__ __launch_bounds__(256)
void prep_kernel(const float* __restrict__ xyz1, const float* __restrict__ xyz2,
                 const float* __restrict__ points2,
                 const float* __restrict__ w0, const float* __restrict__ w1)
{
    __shared__ __align__(16) char shmem[33280];

    if (blockIdx.x < 128) {
        float4* sp = (float4*)shmem;
        const int bx = blockIdx.x & 15;
        const int b  = blockIdx.x >> 4;
        const int t  = threadIdx.x;

        const float* x2 = xyz2 + (size_t)b * 3 * SPTS;
        for (int s = t; s < SPTS; s += 256) {
            float x = x2[s], y = x2[SPTS + s], z = x2[2 * SPTS + s];
            sp[s] = make_float4(-2.f * x, -2.f * y, -2.f * z, x * x + y * y + z * z);
        }
        __syncthreads();

        const int nA = bx * 512 + t;
        const int nB = nA + 256;
        const float* x1 = xyz1 + (size_t)b * 3 * NPTS;
        const float ax = x1[nA], ay = x1[NPTS + nA], az = x1[2 * NPTS + nA];
        const float bx2 = x1[nB], by = x1[NPTS + nB], bz = x1[2 * NPTS + nB];

        float a0 = 3.4e38f, a1 = 3.4e38f, a2 = 3.4e38f;
        float b0 = 3.4e38f, b1 = 3.4e38f, b2 = 3.4e38f;
        int ai0 = 0, ai1 = 0, ai2 = 0, bi0 = 0, bi1 = 0, bi2 = 0;

#pragma unroll 4
        for (int s = 0; s < SPTS; ++s) {
            float4 p = sp[s];
            float ka = fmaf(p.x, ax, fmaf(p.y, ay, fmaf(p.z, az, p.w)));
            float kb = fmaf(p.x, bx2, fmaf(p.y, by, fmaf(p.z, bz, p.w)));
            if (ka < a2) {
                if (ka < a1) {
                    a2 = a1; ai2 = ai1;
                    if (ka < a0) { a1 = a0; ai1 = ai0; a0 = ka; ai0 = s; }
                    else         { a1 = ka; ai1 = s; }
                } else { a2 = ka; ai2 = s; }
            }
            if (kb < b2) {
                if (kb < b1) {
                    b2 = b1; bi2 = bi1;
                    if (kb < b0) { b1 = b0; bi1 = bi0; b0 = kb; bi0 = s; }
                    else         { b1 = kb; bi1 = s; }
                } else { b2 = kb; bi2 = s; }
            }
        }

        {
            const float sn = ax * ax + ay * ay + az * az;
            float r0 = 1.f / (a0 + sn + 1e-8f), r1 = 1.f / (a1 + sn + 1e-8f),
                  r2 = 1.f / (a2 + sn + 1e-8f);
            float ws = r0 + r1 + r2;
            uint4 o;
            o.x = (uint32_t)ai0 | ((uint32_t)ai1 << 16);
            o.y = (uint32_t)ai2;
            o.z = __float_as_uint(r0 / ws);
            o.w = __float_as_uint(r1 / ws);
            d_nn[b * NPTS + nA] = o;
        }
        {
            const float sn = bx2 * bx2 + by * by + bz * bz;
            float r0 = 1.f / (b0 + sn + 1e-8f), r1 = 1.f / (b1 + sn + 1e-8f),
                  r2 = 1.f / (b2 + sn + 1e-8f);
            float ws = r0 + r1 + r2;
            uint4 o;
            o.x = (uint32_t)bi0 | ((uint32_t)bi1 << 16);
            o.y = (uint32_t)bi2;
            o.z = __float_as_uint(r0 / ws);
            o.w = __float_as_uint(r1 / ws);
            d_nn[b * NPTS + nB] = o;
        }
    } else if (blockIdx.x < 640) {
        float (*tile)[260] = (float(*)[260])shmem;
        const int tb = blockIdx.x - 128;
        const int b  = tb >> 6;
        const int s0 = (tb & 63) * 32;
        const int tx = threadIdx.x & 31;
        const int ty = threadIdx.x >> 5;

        const float* src = points2 + (size_t)b * C0 * SPTS;
#pragma unroll
        for (int k = 0; k < 32; k++) {
            const int ch = ty + k * 8;
            tile[tx][ch] = src[(size_t)ch * SPTS + s0 + tx];
        }
        __syncthreads();

        const int w = threadIdx.x >> 5, lane = threadIdx.x & 31;
#pragma unroll
        for (int k = 0; k < 4; k++) {
            const int s = w + k * 8;
            __half* dst = d_P2T + ((size_t)b * SPTS + s0 + s) * C0;
            const float* sp2 = &tile[s][lane * 8];
            uint4 o;
            o.x = pack_h2(sp2[0], sp2[1]);
            o.y = pack_h2(sp2[2], sp2[3]);
            o.z = pack_h2(sp2[4], sp2[5]);
            o.w = pack_h2(sp2[6], sp2[7]);
            *(uint4*)(dst + lane * 8) = o;
        }
    } else {
        const int wb = blockIdx.x - 640;
        if (wb == 0)
            for (int i = threadIdx.x; i < 768; i += 256) d_stats[i] = 0.f;
        int i = wb * 256 + threadIdx.x;
        if (i < C0 * CIN) d_W0h[i] = __float2half_rn(w0[i]);
        int j = i - C0 * CIN;
        if (j >= 0 && j < C1 * C0) d_W1h[j] = __float2half_rn(w1[j]);
    }
}

// ---------------------------------------------------------------------------
// Fused X-builder: warp-per-point; fp16 P2T gathers. (identical to R14)
// ---------------------------------------------------------------------------
__global__ __launch_bounds__(256)
void fused_x_kernel(const float* __restrict__ points1)
{
    __shared__ float tile[32][132];
    const int m0 = blockIdx.x * 32;
    const int b  = m0 >> 13;
    const int n0 = m0 & 8191;
    const int tx = threadIdx.x & 31;
    const int ty = threadIdx.x >> 5;

    const float* p1 = points1 + (size_t)b * C1 * NPTS;
#pragma unroll
    for (int k = 0; k < 16; k++) {
        const int ch = ty + k * 8;
        tile[tx][ch] = p1[(size_t)ch * NPTS + n0 + tx];
    }
    __syncthreads();

    const int w = threadIdx.x >> 5, lane = threadIdx.x & 31;
    const __half* p2t = d_P2T + (size_t)b * SPTS * C0;

#pragma unroll
    for (int k = 0; k < 4; k++) {
        const int pt = w * 4 + k;
        const int m  = m0 + pt;
        const uint4 nn = d_nn[m];
        const int i0 = nn.x & 0xFFFF, i1 = nn.x >> 16, i2 = nn.y;
        const float w0 = __uint_as_float(nn.z);
        const float w1 = __uint_as_float(nn.w);
        const float w2 = 1.f - w0 - w1;

        uint4 ra = *(const uint4*)(p2t + (size_t)i0 * C0 + lane * 8);
        uint4 rc = *(const uint4*)(p2t + (size_t)i1 * C0 + lane * 8);
        uint4 re = *(const uint4*)(p2t + (size_t)i2 * C0 + lane * 8);

        uint4 H;
        {
            const __half2* ha = (const __half2*)&ra;
            const __half2* hc = (const __half2*)&rc;
            const __half2* he = (const __half2*)&re;
#pragma unroll
            for (int j = 0; j < 4; j++) {
                float2 fa = __half22float2(ha[j]);
                float2 fc = __half22float2(hc[j]);
                float2 fe = __half22float2(he[j]);
                float v0 = fmaf(fa.x, w0, fmaf(fc.x, w1, fe.x * w2));
                float v1 = fmaf(fa.y, w0, fmaf(fc.y, w1, fe.y * w2));
                (&H.x)[j] = pack_h2(v0, v1);
            }
        }
        __half* xh = d_Xh + (size_t)m * CIN;
        *(uint4*)(xh + lane * 8) = H;

        {
            float4 v = *(const float4*)(&tile[pt][lane * 4]);
            uint2 h;
            h.x = pack_h2(v.x, v.y);
            h.y = pack_h2(v.z, v.w);
            *(uint2*)(xh + C0 + lane * 4) = h;
        }
    }
}

// ---------------------------------------------------------------------------
// GEMM0 (mma.sync fp16): Y[m][o] = X[m][:].W0[o][:], K=384.
// Hoisted swizzle address math in the MMA loop.
// ---------------------------------------------------------------------------
#define G0_STG  32768
#define G0_SMEM 69632

__global__ __launch_bounds__(256, 2)
void gemm0_kernel()
{
    extern __shared__ char smem[];
    const uint32_t sb = smem_u32(smem);
    const int tid = threadIdx.x;
    const int m0 = blockIdx.x * 128;
    const int ct = blockIdx.y;
    const int w = tid >> 5, lane = tid & 31;
    const int wm = w >> 2, wn = w & 3;
    const int lrow = lane & 15, lch = lane >> 4;

    // hoisted swizzle constants: SW128(row*128 + kc) = row*128 + (kc ^ ((row&7)<<4))
    uint32_t rA[4], xA[4], rB[2], xB[2];
#pragma unroll
    for (int mf = 0; mf < 4; mf++) {
        int row = wm * 64 + mf * 16 + lrow;
        rA[mf] = row * 128;
        xA[mf] = (row & 7) << 4;
    }
#pragma unroll
    for (int p = 0; p < 2; p++) {
        int row = wn * 32 + p * 16 + lrow;
        rB[p] = row * 128;
        xB[p] = (row & 7) << 4;
    }

    float acc[4][4][4];
#pragma unroll
    for (int i = 0; i < 4; i++)
#pragma unroll
        for (int j = 0; j < 4; j++)
#pragma unroll
            for (int q = 0; q < 4; q++) acc[i][j][q] = 0.f;

    auto load_chunk = [&](int c, int stage) {
        const int k0 = c * 64;
        const uint32_t stg = sb + stage * G0_STG;
#pragma unroll
        for (int it = 0; it < 8; it++) {
            int u = it * 256 + tid;
            int arr = u >> 10;
            int v = u & 1023;
            int row = v >> 3, un = v & 7;
            uint32_t dst = stg + arr * 16384 + SW128(row * 128 + un * 16);
            const __half* src;
            if (arr == 0) src = d_W0h + (size_t)(ct * 128 + row) * CIN + k0 + un * 8;
            else          src = d_Xh  + (size_t)(m0 + row) * CIN + k0 + un * 8;
            cp_async16(dst, src);
        }
        CP_COMMIT();
    };

    load_chunk(0, 0);
    load_chunk(1, 1);

    for (int c = 0; c < 6; c++) {
        if (c < 5) asm volatile("cp.async.wait_group 1;" ::: "memory");
        else       asm volatile("cp.async.wait_group 0;" ::: "memory");
        __syncthreads();

        const uint32_t stg = sb + (c & 1) * G0_STG;
        const uint32_t aH = stg, bHb = stg + 16384;
#pragma unroll
        for (int kk = 0; kk < 4; kk++) {
            const uint32_t kc = (kk * 2 + lch) * 16;
            uint32_t Ah[4][4], Bh[4][2];
#pragma unroll
            for (int mf = 0; mf < 4; mf++)
                ldsm_x4(Ah[mf], aH + rA[mf] + (kc ^ xA[mf]));
#pragma unroll
            for (int p = 0; p < 2; p++) {
                uint32_t r[4];
                ldsm_x4(r, bHb + rB[p] + (kc ^ xB[p]));
                Bh[2 * p][0] = r[0]; Bh[2 * p][1] = r[2];
                Bh[2 * p + 1][0] = r[1]; Bh[2 * p + 1][1] = r[3];
            }
#pragma unroll
            for (int mf = 0; mf < 4; mf++)
#pragma unroll
                for (int nf = 0; nf < 4; nf++)
                    mma_f16(acc[mf][nf], Ah[mf], Bh[nf]);
        }
        __syncthreads();
        if (c + 2 < 6) load_chunk(c + 2, c & 1);
    }

    // ---- fused BN0 stats (fp32, exact) ----
    float ssum[4][2] = {}, ssq[4][2] = {};
#pragma unroll
    for (int mf = 0; mf < 4; mf++)
#pragma unroll
        for (int nf = 0; nf < 4; nf++) {
            const float* a = acc[mf][nf];
            ssum[mf][0] += a[0] + a[1];
            ssum[mf][1] += a[2] + a[3];
            ssq[mf][0]  += a[0] * a[0] + a[1] * a[1];
            ssq[mf][1]  += a[2] * a[2] + a[3] * a[3];
        }
#pragma unroll
    for (int mf = 0; mf < 4; mf++)
#pragma unroll
        for (int h = 0; h < 2; h++) {
            float s = ssum[mf][h], q = ssq[mf][h];
            s += __shfl_xor_sync(0xffffffffu, s, 1);
            s += __shfl_xor_sync(0xffffffffu, s, 2);
            q += __shfl_xor_sync(0xffffffffu, q, 1);
            q += __shfl_xor_sync(0xffffffffu, q, 2);
            if ((lane & 3) == 0) {
                int ch = ct * 128 + wm * 64 + mf * 16 + (lane >> 2) + h * 8;
                atomicAdd(&d_stats[ch], s);
                atomicAdd(&d_stats[256 + ch], q);
            }
        }

    // ---- smem transpose -> coalesced fp16 d_Y [m][256] ----
    float* st = (float*)smem;
#pragma unroll
    for (int mf = 0; mf < 4; mf++)
#pragma unroll
        for (int nf = 0; nf < 4; nf++) {
            int ch = wm * 64 + mf * 16 + (lane >> 2);
            int pt = wn * 32 + nf * 8 + (lane & 3) * 2;
            st[pt * 132 + ch]           = acc[mf][nf][0];
            st[(pt + 1) * 132 + ch]     = acc[mf][nf][1];
            st[pt * 132 + ch + 8]       = acc[mf][nf][2];
            st[(pt + 1) * 132 + ch + 8] = acc[mf][nf][3];
        }
    __syncthreads();
    {
        const int row = tid >> 1, half = tid & 1;
        __half* dst = d_Y + (size_t)(m0 + row) * C0 + ct * 128 + half * 64;
        const float* sp = st + row * 132 + half * 64;
#pragma unroll
        for (int j = 0; j < 8; j++) {
            float4 a = *(const float4*)(sp + j * 8);
            float4 b = *(const float4*)(sp + j * 8 + 4);
            uint4 o;
            o.x = pack_h2(a.x, a.y);
            o.y = pack_h2(a.z, a.w);
            o.z = pack_h2(b.x, b.y);
            o.w = pack_h2(b.z, b.w);
            *(uint4*)(dst + j * 8) = o;
        }
    }
}

// ---------------------------------------------------------------------------
// GEMM1: Z = relu(aff0(Y)).W1^T, K=256. finalize0 fused (R13-validated);
// produce in packed half2 (HFMA2 + HMAX2). Hoisted swizzle addresses.
// ---------------------------------------------------------------------------
#define G1_STG  32768
#define G1_SMEM (2048 + 2 * G1_STG)

__global__ __launch_bounds__(256, 2)
void gemm1_kernel(const float* __restrict__ g0, const float* __restrict__ be0)
{
    extern __shared__ char smem[];
    const uint32_t sb = smem_u32(smem);
    uint32_t* s_sc = (uint32_t*)smem;            // 128 half2 (channel pairs)
    uint32_t* s_sh = (uint32_t*)(smem + 512);    // 128 half2
    const int tid = threadIdx.x;
    const int m0 = blockIdx.x * 128;
    const int w = tid >> 5, lane = tid & 31;
    const int wm = w >> 2, wn = w & 3;
    const int lrow = lane & 15, lch = lane >> 4;

    // ---- fused finalize0 -> packed half2 affine consts ----
    {
        const int c = tid;
        const float mean = d_stats[c] * (1.f / MTOT);
        const float var  = d_stats[256 + c] * (1.f / MTOT) - mean * mean;
        const float sc   = g0[c] * rsqrtf(var + 1e-5f);
        const float sh   = be0[c] - mean * sc;
        const float sc1  = __shfl_down_sync(0xffffffffu, sc, 1);
        const float sh1  = __shfl_down_sync(0xffffffffu, sh, 1);
        if ((tid & 1) == 0) {
            s_sc[tid >> 1] = pack_h2(sc, sc1);
            s_sh[tid >> 1] = pack_h2(sh, sh1);
        }
    }
    __syncthreads();

    uint32_t rA[4], xA[4], rB[2], xB[2];
#pragma unroll
    for (int mf = 0; mf < 4; mf++) {
        int row = wm * 64 + mf * 16 + lrow;
        rA[mf] = row * 128;
        xA[mf] = (row & 7) << 4;
    }
#pragma unroll
    for (int p = 0; p < 2; p++) {
        int row = wn * 32 + p * 16 + lrow;
        rB[p] = row * 128;
        xB[p] = (row & 7) << 4;
    }

    auto load_chunk = [&](int c, int stage) {
        const int k0 = c * 64;
        const uint32_t stg = sb + 2048 + stage * G1_STG;
#pragma unroll
        for (int it = 0; it < 4; it++) {
            int u = it * 256 + tid;
            int row = u >> 3, un = u & 7;
            uint32_t dst = stg + SW128(row * 128 + un * 16);
            const __half* src = d_W1h + (size_t)row * C0 + k0 + un * 8;
            cp_async16(dst, src);
        }
        CP_COMMIT();
        // B: fp16 Y -> half2 affine+relu -> smem (swizzled)
        const uint32_t bB = stg + 16384;
        const int yrow = tid >> 1;
        const int koff = (tid & 1) * 32;
        const __half* yp = d_Y + (size_t)(m0 + yrow) * C0 + c * 64 + koff;
        const uint32_t* scp = s_sc + (c * 64 + koff) / 2;
        const uint32_t* shp = s_sh + (c * 64 + koff) / 2;
        const __half2 zero2 = __float2half2_rn(0.f);
        uint32_t hi[16];
#pragma unroll
        for (int i = 0; i < 4; i++) {
            uint4 raw = *(const uint4*)(yp + i * 8);
            uint4 scv = *(const uint4*)(scp + i * 4);
            uint4 shv = *(const uint4*)(shp + i * 4);
#pragma unroll
            for (int j = 0; j < 4; j++) {
                __half2 y  = *reinterpret_cast<__half2*>(&(&raw.x)[j]);
                __half2 s2 = *reinterpret_cast<__half2*>(&(&scv.x)[j]);
                __half2 h2 = *reinterpret_cast<__half2*>(&(&shv.x)[j]);
                __half2 x  = __hmax2(__hfma2(y, s2, h2), zero2);
                hi[i * 4 + j] = *reinterpret_cast<uint32_t*>(&x);
            }
        }
#pragma unroll
        for (int uu = 0; uu < 4; uu++) {
            uint32_t off = SW128(yrow * 128 + ((tid & 1) * 4 + uu) * 16);
            asm volatile("st.shared.v4.b32 [%0], {%1,%2,%3,%4};"
                         :: "r"(bB + off), "r"(hi[uu * 4]), "r"(hi[uu * 4 + 1]),
                            "r"(hi[uu * 4 + 2]), "r"(hi[uu * 4 + 3]) : "memory");
        }
    };

    float acc[4][4][4];
#pragma unroll
    for (int i = 0; i < 4; i++)
#pragma unroll
        for (int j = 0; j < 4; j++)
#pragma unroll
            for (int q = 0; q < 4; q++) acc[i][j][q] = 0.f;

    load_chunk(0, 0);
    load_chunk(1, 1);

    for (int c = 0; c < 4; c++) {
        if (c < 3) asm volatile("cp.async.wait_group 1;" ::: "memory");
        else       asm volatile("cp.async.wait_group 0;" ::: "memory");
        __syncthreads();

        const uint32_t stg = sb + 2048 + (c & 1) * G1_STG;
        const uint32_t aH = stg, bHb = stg + 16384;
#pragma unroll
        for (int kk = 0; kk < 4; kk++) {
            const uint32_t kc = (kk * 2 + lch) * 16;
            uint32_t Ah[4][4], Bh[4][2];
#pragma unroll
            for (int mf = 0; mf < 4; mf++)
                ldsm_x4(Ah[mf], aH + rA[mf] + (kc ^ xA[mf]));
#pragma unroll
            for (int p = 0; p < 2; p++) {
                uint32_t r[4];
                ldsm_x4(r, bHb + rB[p] + (kc ^ xB[p]));
                Bh[2 * p][0] = r[0]; Bh[2 * p][1] = r[2];
                Bh[2 * p + 1][0] = r[1]; Bh[2 * p + 1][1] = r[3];
            }
#pragma unroll
            for (int mf = 0; mf < 4; mf++)
#pragma unroll
                for (int nf = 0; nf < 4; nf++)
                    mma_f16(acc[mf][nf], Ah[mf], Bh[nf]);
        }
        __syncthreads();
        if (c + 2 < 4) load_chunk(c + 2, c & 1);
    }

    // ---- fused BN1 stats (fp32, exact) ----
    float ssum[4][2] = {}, ssq[4][2] = {};
#pragma unroll
    for (int mf = 0; mf < 4; mf++)
#pragma unroll
        for (int nf = 0; nf < 4; nf++) {
            const float* a = acc[mf][nf];
            ssum[mf][0] += a[0] + a[1];
            ssum[mf][1] += a[2] + a[3];
            ssq[mf][0]  += a[0] * a[0] + a[1] * a[1];
            ssq[mf][1]  += a[2] * a[2] + a[3] * a[3];
        }
#pragma unroll
    for (int mf = 0; mf < 4; mf++)
#pragma unroll
        for (int h = 0; h < 2; h++) {
            float s = ssum[mf][h], q = ssq[mf][h];
            s += __shfl_xor_sync(0xffffffffu, s, 1);
            s += __shfl_xor_sync(0xffffffffu, s, 2);
            q += __shfl_xor_sync(0xffffffffu, q, 1);
            q += __shfl_xor_sync(0xffffffffu, q, 2);
            if ((lane & 3) == 0) {
                int ch = wm * 64 + mf * 16 + (lane >> 2) + h * 8;
                atomicAdd(&d_stats[512 + ch], s);
                atomicAdd(&d_stats[640 + ch], q);
            }
        }

    // ---- store fp16 d_Z [c][m] ----
#pragma unroll
    for (int mf = 0; mf < 4; mf++)
#pragma unroll
        for (int nf = 0; nf < 4; nf++) {
            int ch = wm * 64 + mf * 16 + (lane >> 2);
            int pt = m0 + wn * 32 + nf * 8 + (lane & 3) * 2;
            *(uint32_t*)(d_Z + (size_t)ch * MTOT + pt) =
                pack_h2(acc[mf][nf][0], acc[mf][nf][1]);
            *(uint32_t*)(d_Z + (size_t)(ch + 8) * MTOT + pt) =
                pack_h2(acc[mf][nf][2], acc[mf][nf][3]);
        }
}

// ---------------------------------------------------------------------------
// output: fused finalize1 + BN1 affine + ReLU + [B,128,N] store.
// ---------------------------------------------------------------------------
__global__ __launch_bounds__(256)
void output_kernel(float* __restrict__ out, const float* __restrict__ g1,
                   const float* __restrict__ be1)
{
    const int i = blockIdx.x * 256 + threadIdx.x;
    const int base = i * 8;
    const int o = base >> 16;
    const int m = base & 65535;
    const int b = m >> 13;
    const int n = m & 8191;
    // finalize1 (o warp-uniform -> broadcast loads)
    const float mean = d_stats[512 + o] * (1.f / MTOT);
    const float var  = d_stats[640 + o] * (1.f / MTOT) - mean * mean;
    const float sc   = g1[o] * rsqrtf(var + 1e-5f);
    const float sh   = be1[o] - mean * sc;

    uint4 raw = *(const uint4*)(d_Z + (size_t)o * MTOT + m);
    float2 f0 = __half22float2(*reinterpret_cast<__half2*>(&raw.x));
    float2 f1 = __half22float2(*reinterpret_cast<__half2*>(&raw.y));
    float2 f2 = __half22float2(*reinterpret_cast<__half2*>(&raw.z));
    float2 f3 = __half22float2(*reinterpret_cast<__half2*>(&raw.w));
    float4 v0, v1;
    v0.x = fmaxf(fmaf(f0.x, sc, sh), 0.f);
    v0.y = fmaxf(fmaf(f0.y, sc, sh), 0.f);
    v0.z = fmaxf(fmaf(f1.x, sc, sh), 0.f);
    v0.w = fmaxf(fmaf(f1.y, sc, sh), 0.f);
    v1.x = fmaxf(fmaf(f2.x, sc, sh), 0.f);
    v1.y = fmaxf(fmaf(f2.y, sc, sh), 0.f);
    v1.z = fmaxf(fmaf(f3.x, sc, sh), 0.f);
    v1.w = fmaxf(fmaf(f3.y, sc, sh), 0.f);
    float* dst = out + ((size_t)b * C1 + o) * NPTS + n;
    *(float4*)(dst)     = v0;
    *(float4*)(dst + 4) = v1;
}

// ---------------------------------------------------------------------------
extern "C" void kernel_launch(void* const* d_in, const int* in_sizes, int n_in,
                              void* d_out, int out_size)
{
    const float* xyz1    = (const float*)d_in[0];
    const float* xyz2    = (const float*)d_in[1];
    const float* points1 = (const float*)d_in[2];
    const float* points2 = (const float*)d_in[3];
    const float* w0      = (const float*)d_in[4];
    const float* g0      = (const float*)d_in[6];
    const float* be0     = (const float*)d_in[7];
    const float* w1      = (const float*)d_in[8];
    const float* g1      = (const float*)d_in[10];
    const float* be1     = (const float*)d_in[11];
    float* out = (float*)d_out;

    cudaFuncSetAttribute(gemm0_kernel, cudaFuncAttributeMaxDynamicSharedMemorySize, G0_SMEM);
    cudaFuncSetAttribute(gemm1_kernel, cudaFuncAttributeMaxDynamicSharedMemorySize, G1_SMEM);

    prep_kernel<<<1152, 256>>>(xyz1, xyz2, points2, w0, w1);     // (1)
    fused_x_kernel<<<MTOT / 32, 256>>>(points1);                 // (2)
    gemm0_kernel<<<dim3(MTOT / 128, 2), 256, G0_SMEM>>>();       // (3)
    gemm1_kernel<<<MTOT / 128, 256, G1_SMEM>>>(g0, be0);         // (4) <- profiled
    output_kernel<<<(C1 * MTOT / 8) / 256, 256>>>(out, g1, be1); // (5)
}

// round 16
// speedup vs baseline: 1.9670x; 1.2295x over previous
#include <cuda_runtime.h>
#include <cuda_fp16.h>
#include <cstdint>

#define BATCH 8
#define NPTS  8192
#define SPTS  2048
#define MTOT  65536
#define CIN   384
#define C0    256
#define C1    128

// ------------------------- device scratch -------------------------
__device__ __half d_Xh[(size_t)MTOT * CIN];          // [m][384] fp16, k-contiguous
__device__ __half d_Y[(size_t)MTOT * C0];            // [m][256] fp16 (raw conv0 out)
__device__ __half d_Z[(size_t)C1 * MTOT];            // [c][m]   fp16 (raw conv1 out)
__device__ __half d_P2T[(size_t)BATCH * SPTS * C0];  // [b][s][256] fp16
__device__ __half d_W0h[C0 * CIN];                   // [256][384]
__device__ __half d_W1h[C1 * C0];                    // [128][256]
__device__ uint4  d_nnp_i[4][MTOT];                  // per-seg: i0|i1<<16, i2, bits(k0), bits(k1)
__device__ float2 d_nnp_k[4][MTOT];                  // per-seg: k2, sn
__device__ float  d_stats[768];                      // sum0,sq0 | sum1,sq1

// ------------------------- helpers -------------------------
__device__ __forceinline__ uint32_t smem_u32(const void* p) {
    uint32_t a;
    asm("{ .reg .u64 t; cvta.to.shared.u64 t, %1; cvt.u32.u64 %0, t; }" : "=r"(a) : "l"(p));
    return a;
}
#define SW128(o) ((o) ^ (((o) >> 3) & 0x70))
#define CP_COMMIT() asm volatile("cp.async.commit_group;" ::: "memory")

__device__ __forceinline__ void cp_async16(uint32_t dst, const void* src) {
    size_t g = __cvta_generic_to_global(src);
    asm volatile("cp.async.cg.shared.global [%0], [%1], 16;" :: "r"(dst), "l"(g));
}
__device__ __forceinline__ void ldsm_x4(uint32_t (&r)[4], uint32_t addr) {
    asm volatile("ldmatrix.sync.aligned.m8n8.x4.shared.b16 {%0,%1,%2,%3}, [%4];"
                 : "=r"(r[0]), "=r"(r[1]), "=r"(r[2]), "=r"(r[3]) : "r"(addr));
}
__device__ __forceinline__ void mma_f16(float (&c)[4], const uint32_t (&a)[4],
                                        const uint32_t (&b)[2]) {
    asm volatile(
        "mma.sync.aligned.m16n8k16.row.col.f32.f16.f16.f32 "
        "{%0,%1,%2,%3}, {%4,%5,%6,%7}, {%8,%9}, {%0,%1,%2,%3};"
        : "+f"(c[0]), "+f"(c[1]), "+f"(c[2]), "+f"(c[3])
        : "r"(a[0]), "r"(a[1]), "r"(a[2]), "r"(a[3]), "r"(b[0]), "r"(b[1]));
}
__device__ __forceinline__ uint32_t pack_h2(float v0, float v1) {
    __half2 h = __floats2half2_rn(v0, v1);
    return *reinterpret_cast<uint32_t*>(&h);
}
__device__ __forceinline__ void knn_insert(float key, int s, float& k0, float& k1,
                                           float& k2, int& i0, int& i1, int& i2)
{
    if (key < k2) {
        if (key < k1) {
            k2 = k1; i2 = i1;
            if (key < k0) { k1 = k0; i1 = i0; k0 = key; i0 = s; }
            else          { k1 = key; i1 = s; }
        } else { k2 = key; i2 = s; }
    }
}

// ---------------------------------------------------------------------------
// prep: [0,512) knn partial scans (512-candidate segment per block, 2 pts/thr)
//       [512,1024) points2 transpose -> fp16 P2T
//       [1024,1536) W0/W1 -> fp16 (+ stats zero)
// ---------------------------------------------------------------------------
__global__ __launch_bounds__(256)
void prep_kernel(const float* __restrict__ xyz1, const float* __restrict__ xyz2,
                 const float* __restrict__ points2,
                 const float* __restrict__ w0, const float* __restrict__ w1)
{
    __shared__ __align__(16) char shmem[33280];

    if (blockIdx.x < 512) {
        // ---------------- kNN partial: segment of 512 candidates ----------------
        float4* sp = (float4*)shmem;   // 512 float4 = 8KB
        const int b   = blockIdx.x >> 6;
        const int seg = (blockIdx.x >> 4) & 3;
        const int bx  = blockIdx.x & 15;
        const int t   = threadIdx.x;
        const int sbase = seg * 512;

        const float* x2 = xyz2 + (size_t)b * 3 * SPTS;
        for (int s = t; s < 512; s += 256) {
            float x = x2[sbase + s], y = x2[SPTS + sbase + s], z = x2[2 * SPTS + sbase + s];
            sp[s] = make_float4(-2.f * x, -2.f * y, -2.f * z, x * x + y * y + z * z);
        }
        __syncthreads();

        const int nA = bx * 512 + t;
        const int nB = nA + 256;
        const float* x1 = xyz1 + (size_t)b * 3 * NPTS;
        const float ax = x1[nA], ay = x1[NPTS + nA], az = x1[2 * NPTS + nA];
        const float bx2 = x1[nB], by = x1[NPTS + nB], bz = x1[2 * NPTS + nB];

        float a0 = 3.4e38f, a1 = 3.4e38f, a2 = 3.4e38f;
        float b0 = 3.4e38f, b1 = 3.4e38f, b2 = 3.4e38f;
        int ai0 = 0, ai1 = 0, ai2 = 0, bi0 = 0, bi1 = 0, bi2 = 0;

#pragma unroll 4
        for (int s = 0; s < 512; ++s) {
            float4 p = sp[s];
            float ka = fmaf(p.x, ax, fmaf(p.y, ay, fmaf(p.z, az, p.w)));
            float kb = fmaf(p.x, bx2, fmaf(p.y, by, fmaf(p.z, bz, p.w)));
            knn_insert(ka, s, a0, a1, a2, ai0, ai1, ai2);
            knn_insert(kb, s, b0, b1, b2, bi0, bi1, bi2);
        }

        {
            const int m = b * NPTS + nA;
            const float sn = ax * ax + ay * ay + az * az;
            uint4 pi;
            pi.x = (uint32_t)(sbase + ai0) | ((uint32_t)(sbase + ai1) << 16);
            pi.y = (uint32_t)(sbase + ai2);
            pi.z = __float_as_uint(a0);
            pi.w = __float_as_uint(a1);
            d_nnp_i[seg][m] = pi;
            d_nnp_k[seg][m] = make_float2(a2, sn);
        }
        {
            const int m = b * NPTS + nB;
            const float sn = bx2 * bx2 + by * by + bz * bz;
            uint4 pi;
            pi.x = (uint32_t)(sbase + bi0) | ((uint32_t)(sbase + bi1) << 16);
            pi.y = (uint32_t)(sbase + bi2);
            pi.z = __float_as_uint(b0);
            pi.w = __float_as_uint(b1);
            d_nnp_i[seg][m] = pi;
            d_nnp_k[seg][m] = make_float2(b2, sn);
        }
    } else if (blockIdx.x < 1024) {
        // ---------------- points2 transpose ----------------
        float (*tile)[260] = (float(*)[260])shmem;
        const int tb = blockIdx.x - 512;
        const int b  = tb >> 6;
        const int s0 = (tb & 63) * 32;
        const int tx = threadIdx.x & 31;
        const int ty = threadIdx.x >> 5;

        const float* src = points2 + (size_t)b * C0 * SPTS;
#pragma unroll
        for (int k = 0; k < 32; k++) {
            const int ch = ty + k * 8;
            tile[tx][ch] = src[(size_t)ch * SPTS + s0 + tx];
        }
        __syncthreads();

        const int w = threadIdx.x >> 5, lane = threadIdx.x & 31;
#pragma unroll
        for (int k = 0; k < 4; k++) {
            const int s = w + k * 8;
            __half* dst = d_P2T + ((size_t)b * SPTS + s0 + s) * C0;
            const float* sp2 = &tile[s][lane * 8];
            uint4 o;
            o.x = pack_h2(sp2[0], sp2[1]);
            o.y = pack_h2(sp2[2], sp2[3]);
            o.z = pack_h2(sp2[4], sp2[5]);
            o.w = pack_h2(sp2[6], sp2[7]);
            *(uint4*)(dst + lane * 8) = o;
        }
    } else {
        // ---------------- W conversion + stats zero ----------------
        const int wb = blockIdx.x - 1024;
        if (wb == 0)
            for (int i = threadIdx.x; i < 768; i += 256) d_stats[i] = 0.f;
        int i = wb * 256 + threadIdx.x;
        if (i < C0 * CIN) d_W0h[i] = __float2half_rn(w0[i]);
        int j = i - C0 * CIN;
        if (j >= 0 && j < C1 * C0) d_W1h[j] = __float2half_rn(w1[j]);
    }
}

// ---------------------------------------------------------------------------
// Fused X-builder: warp-per-point. Prologue merges the 4 knn partials
// (exact: same insert order as a sequential scan), then fp16 gathers.
// ---------------------------------------------------------------------------
__global__ __launch_bounds__(256)
void fused_x_kernel(const float* __restrict__ points1)
{
    __shared__ float tile[32][132];
    const int m0 = blockIdx.x * 32;
    const int b  = m0 >> 13;
    const int n0 = m0 & 8191;
    const int tx = threadIdx.x & 31;
    const int ty = threadIdx.x >> 5;

    const float* p1 = points1 + (size_t)b * C1 * NPTS;
#pragma unroll
    for (int k = 0; k < 16; k++) {
        const int ch = ty + k * 8;
        tile[tx][ch] = p1[(size_t)ch * NPTS + n0 + tx];
    }
    __syncthreads();

    const int w = threadIdx.x >> 5, lane = threadIdx.x & 31;
    const __half* p2t = d_P2T + (size_t)b * SPTS * C0;

#pragma unroll
    for (int k = 0; k < 4; k++) {
        const int pt = w * 4 + k;
        const int m  = m0 + pt;

        // ---- merge 4 sorted partials (warp-uniform broadcast loads) ----
        float k0 = 3.4e38f, k1 = 3.4e38f, k2 = 3.4e38f;
        int i0 = 0, i1 = 0, i2 = 0;
        float sn = 0.f;
#pragma unroll
        for (int seg = 0; seg < 4; seg++) {
            const uint4  pi = d_nnp_i[seg][m];
            const float2 pk = d_nnp_k[seg][m];
            knn_insert(__uint_as_float(pi.z), pi.x & 0xFFFF, k0, k1, k2, i0, i1, i2);
            knn_insert(__uint_as_float(pi.w), pi.x >> 16,    k0, k1, k2, i0, i1, i2);
            knn_insert(pk.x,                  pi.y,          k0, k1, k2, i0, i1, i2);
            sn = pk.y;
        }
        const float r0w = 1.f / (k0 + sn + 1e-8f);
        const float r1w = 1.f / (k1 + sn + 1e-8f);
        const float r2w = 1.f / (k2 + sn + 1e-8f);
        const float ws = r0w + r1w + r2w;
        const float w0 = r0w / ws, w1 = r1w / ws;
        const float w2 = 1.f - w0 - w1;

        uint4 ra = *(const uint4*)(p2t + (size_t)i0 * C0 + lane * 8);
        uint4 rc = *(const uint4*)(p2t + (size_t)i1 * C0 + lane * 8);
        uint4 re = *(const uint4*)(p2t + (size_t)i2 * C0 + lane * 8);

        uint4 H;
        {
            const __half2* ha = (const __half2*)&ra;
            const __half2* hc = (const __half2*)&rc;
            const __half2* he = (const __half2*)&re;
#pragma unroll
            for (int j = 0; j < 4; j++) {
                float2 fa = __half22float2(ha[j]);
                float2 fc = __half22float2(hc[j]);
                float2 fe = __half22float2(he[j]);
                float v0 = fmaf(fa.x, w0, fmaf(fc.x, w1, fe.x * w2));
                float v1 = fmaf(fa.y, w0, fmaf(fc.y, w1, fe.y * w2));
                (&H.x)[j] = pack_h2(v0, v1);
            }
        }
        __half* xh = d_Xh + (size_t)m * CIN;
        *(uint4*)(xh + lane * 8) = H;

        {
            float4 v = *(const float4*)(&tile[pt][lane * 4]);
            uint2 h;
            h.x = pack_h2(v.x, v.y);
            h.y = pack_h2(v.z, v.w);
            *(uint2*)(xh + C0 + lane * 4) = h;
        }
    }
}

// ---------------------------------------------------------------------------
// GEMM0 (mma.sync fp16): Y[m][o] = X[m][:].W0[o][:], K=384.
// Hoisted swizzle math in MMA loop AND affine producer addressing.
// ---------------------------------------------------------------------------
#define G0_STG  32768
#define G0_SMEM 69632

__global__ __launch_bounds__(256, 2)
void gemm0_kernel()
{
    extern __shared__ char smem[];
    const uint32_t sb = smem_u32(smem);
    const int tid = threadIdx.x;
    const int m0 = blockIdx.x * 128;
    const int ct = blockIdx.y;
    const int w = tid >> 5, lane = tid & 31;
    const int wm = w >> 2, wn = w & 3;
    const int lrow = lane & 15, lch = lane >> 4;

    uint32_t rA[4], xA[4], rB[2], xB[2];
#pragma unroll
    for (int mf = 0; mf < 4; mf++) {
        int row = wm * 64 + mf * 16 + lrow;
        rA[mf] = row * 128;
        xA[mf] = (row & 7) << 4;
    }
#pragma unroll
    for (int p = 0; p < 2; p++) {
        int row = wn * 32 + p * 16 + lrow;
        rB[p] = row * 128;
        xB[p] = (row & 7) << 4;
    }

    // producer: affine addressing (row = tid>>3 + it*32, un const; +32 rows
    // adds 4096B to dst without touching swizzle bits)
    const int pr0 = tid >> 3;
    const int pun = (tid & 7) * 8;
    const uint32_t dstOff = SW128(pr0 * 128 + (tid & 7) * 16);
    const __half* srcW = d_W0h + (size_t)(ct * 128 + pr0) * CIN + pun;
    const __half* srcX = d_Xh  + (size_t)(m0 + pr0) * CIN + pun;

    float acc[4][4][4];
#pragma unroll
    for (int i = 0; i < 4; i++)
#pragma unroll
        for (int j = 0; j < 4; j++)
#pragma unroll
            for (int q = 0; q < 4; q++) acc[i][j][q] = 0.f;

    auto load_chunk = [&](int c, int stage) {
        const uint32_t stg = sb + stage * G0_STG;
        const __half* sw = srcW + c * 64;
        const __half* sx = srcX + c * 64;
#pragma unroll
        for (int it = 0; it < 4; it++) {
            cp_async16(stg + dstOff + it * 4096, sw + (size_t)it * 32 * CIN);
            cp_async16(stg + 16384 + dstOff + it * 4096, sx + (size_t)it * 32 * CIN);
        }
        CP_COMMIT();
    };

    load_chunk(0, 0);
    load_chunk(1, 1);

    for (int c = 0; c < 6; c++) {
        if (c < 5) asm volatile("cp.async.wait_group 1;" ::: "memory");
        else       asm volatile("cp.async.wait_group 0;" ::: "memory");
        __syncthreads();

        const uint32_t stg = sb + (c & 1) * G0_STG;
        const uint32_t aH = stg, bHb = stg + 16384;
#pragma unroll
        for (int kk = 0; kk < 4; kk++) {
            const uint32_t kc = (kk * 2 + lch) * 16;
            uint32_t Ah[4][4], Bh[4][2];
#pragma unroll
            for (int mf = 0; mf < 4; mf++)
                ldsm_x4(Ah[mf], aH + rA[mf] + (kc ^ xA[mf]));
#pragma unroll
            for (int p = 0; p < 2; p++) {
                uint32_t r[4];
                ldsm_x4(r, bHb + rB[p] + (kc ^ xB[p]));
                Bh[2 * p][0] = r[0]; Bh[2 * p][1] = r[2];
                Bh[2 * p + 1][0] = r[1]; Bh[2 * p + 1][1] = r[3];
            }
#pragma unroll
            for (int mf = 0; mf < 4; mf++)
#pragma unroll
                for (int nf = 0; nf < 4; nf++)
                    mma_f16(acc[mf][nf], Ah[mf], Bh[nf]);
        }
        __syncthreads();
        if (c + 2 < 6) load_chunk(c + 2, c & 1);
    }

    // ---- fused BN0 stats (fp32, exact) ----
    float ssum[4][2] = {}, ssq[4][2] = {};
#pragma unroll
    for (int mf = 0; mf < 4; mf++)
#pragma unroll
        for (int nf = 0; nf < 4; nf++) {
            const float* a = acc[mf][nf];
            ssum[mf][0] += a[0] + a[1];
            ssum[mf][1] += a[2] + a[3];
            ssq[mf][0]  += a[0] * a[0] + a[1] * a[1];
            ssq[mf][1]  += a[2] * a[2] + a[3] * a[3];
        }
#pragma unroll
    for (int mf = 0; mf < 4; mf++)
#pragma unroll
        for (int h = 0; h < 2; h++) {
            float s = ssum[mf][h], q = ssq[mf][h];
            s += __shfl_xor_sync(0xffffffffu, s, 1);
            s += __shfl_xor_sync(0xffffffffu, s, 2);
            q += __shfl_xor_sync(0xffffffffu, q, 1);
            q += __shfl_xor_sync(0xffffffffu, q, 2);
            if ((lane & 3) == 0) {
                int ch = ct * 128 + wm * 64 + mf * 16 + (lane >> 2) + h * 8;
                atomicAdd(&d_stats[ch], s);
                atomicAdd(&d_stats[256 + ch], q);
            }
        }

    // ---- smem transpose -> coalesced fp16 d_Y [m][256] ----
    float* st = (float*)smem;
#pragma unroll
    for (int mf = 0; mf < 4; mf++)
#pragma unroll
        for (int nf = 0; nf < 4; nf++) {
            int ch = wm * 64 + mf * 16 + (lane >> 2);
            int pt = wn * 32 + nf * 8 + (lane & 3) * 2;
            st[pt * 132 + ch]           = acc[mf][nf][0];
            st[(pt + 1) * 132 + ch]     = acc[mf][nf][1];
            st[pt * 132 + ch + 8]       = acc[mf][nf][2];
            st[(pt + 1) * 132 + ch + 8] = acc[mf][nf][3];
        }
    __syncthreads();
    {
        const int row = tid >> 1, half = tid & 1;
        __half* dst = d_Y + (size_t)(m0 + row) * C0 + ct * 128 + half * 64;
        const float* sp = st + row * 132 + half * 64;
#pragma unroll
        for (int j = 0; j < 8; j++) {
            float4 a = *(const float4*)(sp + j * 8);
            float4 b = *(const float4*)(sp + j * 8 + 4);
            uint4 o;
            o.x = pack_h2(a.x, a.y);
            o.y = pack_h2(a.z, a.w);
            o.z = pack_h2(b.x, b.y);
            o.w = pack_h2(b.z, b.w);
            *(uint4*)(dst + j * 8) = o;
        }
    }
}

// ---------------------------------------------------------------------------
// GEMM1: Z = relu(aff0(Y)).W1^T, K=256. finalize0 fused; half2 produce;
// hoisted swizzle + affine producer addressing.
// ---------------------------------------------------------------------------
#define G1_STG  32768
#define G1_SMEM (2048 + 2 * G1_STG)

__global__ __launch_bounds__(256, 2)
void gemm1_kernel(const float* __restrict__ g0, const float* __restrict__ be0)
{
    extern __shared__ char smem[];
    const uint32_t sb = smem_u32(smem);
    uint32_t* s_sc = (uint32_t*)smem;            // 128 half2 (channel pairs)
    uint32_t* s_sh = (uint32_t*)(smem + 512);    // 128 half2
    const int tid = threadIdx.x;
    const int m0 = blockIdx.x * 128;
    const int w = tid >> 5, lane = tid & 31;
    const int wm = w >> 2, wn = w & 3;
    const int lrow = lane & 15, lch = lane >> 4;

    // ---- fused finalize0 -> packed half2 affine consts ----
    {
        const int c = tid;
        const float mean = d_stats[c] * (1.f / MTOT);
        const float var  = d_stats[256 + c] * (1.f / MTOT) - mean * mean;
        const float sc   = g0[c] * rsqrtf(var + 1e-5f);
        const float sh   = be0[c] - mean * sc;
        const float sc1  = __shfl_down_sync(0xffffffffu, sc, 1);
        const float sh1  = __shfl_down_sync(0xffffffffu, sh, 1);
        if ((tid & 1) == 0) {
            s_sc[tid >> 1] = pack_h2(sc, sc1);
            s_sh[tid >> 1] = pack_h2(sh, sh1);
        }
    }
    __syncthreads();

    uint32_t rA[4], xA[4], rB[2], xB[2];
#pragma unroll
    for (int mf = 0; mf < 4; mf++) {
        int row = wm * 64 + mf * 16 + lrow;
        rA[mf] = row * 128;
        xA[mf] = (row & 7) << 4;
    }
#pragma unroll
    for (int p = 0; p < 2; p++) {
        int row = wn * 32 + p * 16 + lrow;
        rB[p] = row * 128;
        xB[p] = (row & 7) << 4;
    }

    const int pr0 = tid >> 3;
    const int pun = (tid & 7) * 8;
    const uint32_t dstOffW = SW128(pr0 * 128 + (tid & 7) * 16);
    const __half* srcW = d_W1h + (size_t)pr0 * C0 + pun;

    auto load_chunk = [&](int c, int stage) {
        const uint32_t stg = sb + 2048 + stage * G1_STG;
        const __half* sw = srcW + c * 64;
#pragma unroll
        for (int it = 0; it < 4; it++)
            cp_async16(stg + dstOffW + it * 4096, sw + (size_t)it * 32 * C0);
        CP_COMMIT();
        // B: fp16 Y -> half2 affine+relu -> smem (swizzled)
        const uint32_t bB = stg + 16384;
        const int yrow = tid >> 1;
        const int koff = (tid & 1) * 32;
        const __half* yp = d_Y + (size_t)(m0 + yrow) * C0 + c * 64 + koff;
        const uint32_t* scp = s_sc + (c * 64 + koff) / 2;
        const uint32_t* shp = s_sh + (c * 64 + koff) / 2;
        const __half2 zero2 = __float2half2_rn(0.f);
        uint32_t hi[16];
#pragma unroll
        for (int i = 0; i < 4; i++) {
            uint4 raw = *(const uint4*)(yp + i * 8);
            uint4 scv = *(const uint4*)(scp + i * 4);
            uint4 shv = *(const uint4*)(shp + i * 4);
#pragma unroll
            for (int j = 0; j < 4; j++) {
                __half2 y  = *reinterpret_cast<__half2*>(&(&raw.x)[j]);
                __half2 s2 = *reinterpret_cast<__half2*>(&(&scv.x)[j]);
                __half2 h2 = *reinterpret_cast<__half2*>(&(&shv.x)[j]);
                __half2 x  = __hmax2(__hfma2(y, s2, h2), zero2);
                hi[i * 4 + j] = *reinterpret_cast<uint32_t*>(&x);
            }
        }
#pragma unroll
        for (int uu = 0; uu < 4; uu++) {
            uint32_t off = SW128(yrow * 128 + ((tid & 1) * 4 + uu) * 16);
            asm volatile("st.shared.v4.b32 [%0], {%1,%2,%3,%4};"
                         :: "r"(bB + off), "r"(hi[uu * 4]), "r"(hi[uu * 4 + 1]),
                            "r"(hi[uu * 4 + 2]), "r"(hi[uu * 4 + 3]) : "memory");
        }
    };

    float acc[4][4][4];
#pragma unroll
    for (int i = 0; i < 4; i++)
#pragma unroll
        for (int j = 0; j < 4; j++)
#pragma unroll
            for (int q = 0; q < 4; q++) acc[i][j][q] = 0.f;

    load_chunk(0, 0);
    load_chunk(1, 1);

    for (int c = 0; c < 4; c++) {
        if (c < 3) asm volatile("cp.async.wait_group 1;" ::: "memory");
        else       asm volatile("cp.async.wait_group 0;" ::: "memory");
        __syncthreads();

        const uint32_t stg = sb + 2048 + (c & 1) * G1_STG;
        const uint32_t aH = stg, bHb = stg + 16384;
#pragma unroll
        for (int kk = 0; kk < 4; kk++) {
            const uint32_t kc = (kk * 2 + lch) * 16;
            uint32_t Ah[4][4], Bh[4][2];
#pragma unroll
            for (int mf = 0; mf < 4; mf++)
                ldsm_x4(Ah[mf], aH + rA[mf] + (kc ^ xA[mf]));
#pragma unroll
            for (int p = 0; p < 2; p++) {
                uint32_t r[4];
                ldsm_x4(r, bHb + rB[p] + (kc ^ xB[p]));
                Bh[2 * p][0] = r[0]; Bh[2 * p][1] = r[2];
                Bh[2 * p + 1][0] = r[1]; Bh[2 * p + 1][1] = r[3];
            }
#pragma unroll
            for (int mf = 0; mf < 4; mf++)
#pragma unroll
                for (int nf = 0; nf < 4; nf++)
                    mma_f16(acc[mf][nf], Ah[mf], Bh[nf]);
        }
        __syncthreads();
        if (c + 2 < 4) load_chunk(c + 2, c & 1);
    }

    // ---- fused BN1 stats (fp32, exact) ----
    float ssum[4][2] = {}, ssq[4][2] = {};
#pragma unroll
    for (int mf = 0; mf < 4; mf++)
#pragma unroll
        for (int nf = 0; nf < 4; nf++) {
            const float* a = acc[mf][nf];
            ssum[mf][0] += a[0] + a[1];
            ssum[mf][1] += a[2] + a[3];
            ssq[mf][0]  += a[0] * a[0] + a[1] * a[1];
            ssq[mf][1]  += a[2] * a[2] + a[3] * a[3];
        }
#pragma unroll
    for (int mf = 0; mf < 4; mf++)
#pragma unroll
        for (int h = 0; h < 2; h++) {
            float s = ssum[mf][h], q = ssq[mf][h];
            s += __shfl_xor_sync(0xffffffffu, s, 1);
            s += __shfl_xor_sync(0xffffffffu, s, 2);
            q += __shfl_xor_sync(0xffffffffu, q, 1);
            q += __shfl_xor_sync(0xffffffffu, q, 2);
            if ((lane & 3) == 0) {
                int ch = wm * 64 + mf * 16 + (lane >> 2) + h * 8;
                atomicAdd(&d_stats[512 + ch], s);
                atomicAdd(&d_stats[640 + ch], q);
            }
        }

    // ---- store fp16 d_Z [c][m] ----
#pragma unroll
    for (int mf = 0; mf < 4; mf++)
#pragma unroll
        for (int nf = 0; nf < 4; nf++) {
            int ch = wm * 64 + mf * 16 + (lane >> 2);
            int pt = m0 + wn * 32 + nf * 8 + (lane & 3) * 2;
            *(uint32_t*)(d_Z + (size_t)ch * MTOT + pt) =
                pack_h2(acc[mf][nf][0], acc[mf][nf][1]);
            *(uint32_t*)(d_Z + (size_t)(ch + 8) * MTOT + pt) =
                pack_h2(acc[mf][nf][2], acc[mf][nf][3]);
        }
}

// ---------------------------------------------------------------------------
// output: fused finalize1 + BN1 affine + ReLU + [B,128,N] store.
// ---------------------------------------------------------------------------
__global__ __launch_bounds__(256)
void output_kernel(float* __restrict__ out, const float* __restrict__ g1,
                   const float* __restrict__ be1)
{
    const int i = blockIdx.x * 256 + threadIdx.x;
    const int base = i * 8;
    const int o = base >> 16;
    const int m = base & 65535;
    const int b = m >> 13;
    const int n = m & 8191;
    const float mean = d_stats[512 + o] * (1.f / MTOT);
    const float var  = d_stats[640 + o] * (1.f / MTOT) - mean * mean;
    const float sc   = g1[o] * rsqrtf(var + 1e-5f);
    const float sh   = be1[o] - mean * sc;

    uint4 raw = *(const uint4*)(d_Z + (size_t)o * MTOT + m);
    float2 f0 = __half22float2(*reinterpret_cast<__half2*>(&raw.x));
    float2 f1 = __half22float2(*reinterpret_cast<__half2*>(&raw.y));
    float2 f2 = __half22float2(*reinterpret_cast<__half2*>(&raw.z));
    float2 f3 = __half22float2(*reinterpret_cast<__half2*>(&raw.w));
    float4 v0, v1;
    v0.x = fmaxf(fmaf(f0.x, sc, sh), 0.f);
    v0.y = fmaxf(fmaf(f0.y, sc, sh), 0.f);
    v0.z = fmaxf(fmaf(f1.x, sc, sh), 0.f);
    v0.w = fmaxf(fmaf(f1.y, sc, sh), 0.f);
    v1.x = fmaxf(fmaf(f2.x, sc, sh), 0.f);
    v1.y = fmaxf(fmaf(f2.y, sc, sh), 0.f);
    v1.z = fmaxf(fmaf(f3.x, sc, sh), 0.f);
    v1.w = fmaxf(fmaf(f3.y, sc, sh), 0.f);
    float* dst = out + ((size_t)b * C1 + o) * NPTS + n;
    *(float4*)(dst)     = v0;
    *(float4*)(dst + 4) = v1;
}

// ---------------------------------------------------------------------------
extern "C" void kernel_launch(void* const* d_in, const int* in_sizes, int n_in,
                              void* d_out, int out_size)
{
    const float* xyz1    = (const float*)d_in[0];
    const float* xyz2    = (const float*)d_in[1];
    const float* points1 = (const float*)d_in[2];
    const float* points2 = (const float*)d_in[3];
    const float* w0      = (const float*)d_in[4];
    const float* g0      = (const float*)d_in[6];
    const float* be0     = (const float*)d_in[7];
    const float* w1      = (const float*)d_in[8];
    const float* g1      = (const float*)d_in[10];
    const float* be1     = (const float*)d_in[11];
    float* out = (float*)d_out;

    cudaFuncSetAttribute(gemm0_kernel, cudaFuncAttributeMaxDynamicSharedMemorySize, G0_SMEM);
    cudaFuncSetAttribute(gemm1_kernel, cudaFuncAttributeMaxDynamicSharedMemorySize, G1_SMEM);

    prep_kernel<<<1536, 256>>>(xyz1, xyz2, points2, w0, w1);     // (1)
    fused_x_kernel<<<MTOT / 32, 256>>>(points1);                 // (2)
    gemm0_kernel<<<dim3(MTOT / 128, 2), 256, G0_SMEM>>>();       // (3)
    gemm1_kernel<<<MTOT / 128, 256, G1_SMEM>>>(g0, be0);         // (4) <- profiled
    output_kernel<<<(C1 * MTOT / 8) / 256, 256>>>(out, g1, be1); // (5)
}